// round 6
// baseline (speedup 1.0000x reference)
#include <cuda_runtime.h>
#include <cuda_bf16.h>
#include <cstdint>
#include <cstddef>

// ===========================================================================
// StructureAttention, mma.sync bf16 hi/lo x3, fp32 accum.
// R6: R5 design (128x64 tile, 3x30KB stages, 2 CTAs/SM) with loader OOB fix
// (4 chunks of 16B per 64B row; padding never written/read).
// ===========================================================================

#define C_DIM 256
#define NB    4
#define MTOT  16777216

__device__ float g_Q[MTOT];
__device__ float g_K[MTOT];
__device__ float g_V[MTOT];
__device__ __nv_bfloat16 g_xhi[MTOT], g_xlo[MTOT];
__device__ __nv_bfloat16 g_mhi[MTOT], g_mlo[MTOT];
__device__ __nv_bfloat16 g_lhi[MTOT], g_llo[MTOT];
__device__ __nv_bfloat16 g_hhi[MTOT], g_hlo[MTOT];
__device__ __nv_bfloat16 g_w[917504];
__device__ float g_small[32 * 1024 + 32 * 32];

// ---------------- helpers --------------------------------------------------
__device__ __forceinline__ uint32_t smem_u32(const void* p) {
    uint32_t a;
    asm("{ .reg .u64 t; cvta.to.shared.u64 t, %1; cvt.u32.u64 %0, t; }" : "=r"(a) : "l"(p));
    return a;
}
__device__ __forceinline__ void cp16(uint32_t dst, const void* src) {
    asm volatile("cp.async.cg.shared.global [%0], [%1], 16;"
                 :: "r"(dst), "l"(__cvta_generic_to_global(src)) : "memory");
}
#define CP_COMMIT() asm volatile("cp.async.commit_group;" ::: "memory")
#define CP_WAIT1()  asm volatile("cp.async.wait_group 1;"  ::: "memory")

__device__ __forceinline__ void ldsm4(uint32_t* r, uint32_t addr) {
    asm volatile("ldmatrix.sync.aligned.m8n8.x4.shared.b16 {%0,%1,%2,%3}, [%4];"
                 : "=r"(r[0]), "=r"(r[1]), "=r"(r[2]), "=r"(r[3]) : "r"(addr));
}
__device__ __forceinline__ void mma_bf16(float* c, const uint32_t* a, const uint32_t* b) {
    asm("mma.sync.aligned.m16n8k16.row.col.f32.bf16.bf16.f32 "
        "{%0,%1,%2,%3}, {%4,%5,%6,%7}, {%8,%9}, {%0,%1,%2,%3};"
        : "+f"(c[0]), "+f"(c[1]), "+f"(c[2]), "+f"(c[3])
        : "r"(a[0]), "r"(a[1]), "r"(a[2]), "r"(a[3]), "r"(b[0]), "r"(b[1]));
}
__device__ __forceinline__ void split2(float v, __nv_bfloat16& hi, __nv_bfloat16& lo) {
    hi = __float2bfloat16(v);
    lo = __float2bfloat16(v - __bfloat162float(hi));
}
template <int EPI>
__device__ __forceinline__ float epi_f(float t) {
    if (EPI == 1) return t > 0.f ? t + 1.f : __expf(t);   // phi = elu+1
    if (EPI == 2) return fmaxf(t, 0.f);                   // relu
    return t;
}

// ===========================================================================
// HMMA GEMM: out[M,256] = A[M,KDIM] * W[KDIM,256]; W transposed
// (Wt[256,KDIM]) as bf16 hi/lo planes; A as bf16 hi/lo planes (row len 256;
// KDIM=512 -> second plane pair = cols 256..511).
// CTA 128x64, BK=32, 3-stage cp.async (30KB/stage), 8 warps (4x2),
// warp tile 32x32, 2 CTAs/SM.  acc += Ah*Wh + Ah*Wl + Al*Wh.
// ===========================================================================
#define A_PLANE   10240           // 128 rows * 80B
#define B_PLANE   5120            // 64 rows * 80B
#define STAGE_B   30720           // 2*A_PLANE + 2*B_PLANE
#define GEMM_SMEM (3 * STAGE_B)   // 92160

template <int KDIM, int EPI, int OUTM>
__global__ __launch_bounds__(256, 2)
void gemm_mma(const __nv_bfloat16* __restrict__ A0h, const __nv_bfloat16* __restrict__ A0l,
              const __nv_bfloat16* __restrict__ A1h, const __nv_bfloat16* __restrict__ A1l,
              const __nv_bfloat16* __restrict__ Bh,  const __nv_bfloat16* __restrict__ Bl,
              float* __restrict__ outF,
              __nv_bfloat16* __restrict__ outH, __nv_bfloat16* __restrict__ outL)
{
    extern __shared__ char dsm[];
    const uint32_t sb = smem_u32(dsm);

    const int tid    = threadIdx.x;
    const int lane   = tid & 31;
    const int wid    = tid >> 5;
    const int warp_m = wid >> 1;          // 0..3 (32 rows each)
    const int warp_n = wid & 1;           // 0..1 (32 cols each)
    const int n0     = blockIdx.x * 64;
    const int m0     = blockIdx.y * 128;
    constexpr int NIT = KDIM / 32;

    // loader mapping: A: 256 threads -> 2 planes x 128 rows, 4x16B per row.
    const int a_pl  = tid >> 7;           // 0..1
    const int a_row = tid & 127;
    // B: threads 0..127 -> 2 planes x 64 rows, 4x16B per row.
    const int b_pl  = (tid & 127) >> 6;
    const int b_row = tid & 63;
    const bool b_act = tid < 128;

    float acc[2][4][4];
#pragma unroll
    for (int mt = 0; mt < 2; ++mt)
#pragma unroll
        for (int nt = 0; nt < 4; ++nt)
#pragma unroll
            for (int q = 0; q < 4; ++q) acc[mt][nt][q] = 0.f;

    auto load_stage = [&](int buf, int it) {
        const uint32_t st = sb + buf * STAGE_B;
        const int kc = it * 32;
        const __nv_bfloat16 *Ah, *Al;
        int kk = kc;
        if (KDIM == 512 && kc >= 256) { Ah = A1h; Al = A1l; kk = kc - 256; }
        else                          { Ah = A0h; Al = A0l; }
        {
            const __nv_bfloat16* ap = a_pl ? Al : Ah;
            const __nv_bfloat16* srow = ap + (size_t)(m0 + a_row) * 256 + kk;
            const uint32_t drow = st + a_pl * A_PLANE + a_row * 80;
#pragma unroll
            for (int j = 0; j < 4; ++j) cp16(drow + j * 16, srow + j * 8);
        }
        if (b_act) {
            const __nv_bfloat16* bp = b_pl ? Bl : Bh;
            const __nv_bfloat16* srow = bp + (size_t)(n0 + b_row) * KDIM + kc;
            const uint32_t drow = st + 2 * A_PLANE + b_pl * B_PLANE + b_row * 80;
#pragma unroll
            for (int j = 0; j < 4; ++j) cp16(drow + j * 16, srow + j * 8);
        }
    };

    load_stage(0, 0); CP_COMMIT();
    load_stage(1, 1); CP_COMMIT();

    const int g  = lane >> 3;
    const int li = lane & 7;
    const int a_r  = li + (g & 1) * 8;
    const int a_kb = (g >> 1) * 16;
    const int b_r  = li + (g >> 1) * 8;
    const int b_kb = (g & 1) * 16;

    for (int it = 0; it < NIT; ++it) {
        CP_WAIT1();
        __syncthreads();
        if (it + 2 < NIT) load_stage((it + 2) % 3, it + 2);
        CP_COMMIT();

        const uint32_t st  = sb + (it % 3) * STAGE_B;
        const uint32_t stB = st + 2 * A_PLANE;

#pragma unroll
        for (int ks = 0; ks < 2; ++ks) {
            uint32_t aH[2][4], aL[2][4];
#pragma unroll
            for (int mt = 0; mt < 2; ++mt) {
                const uint32_t ro = (uint32_t)((warp_m * 32 + mt * 16 + a_r) * 80 + ks * 32 + a_kb);
                ldsm4(aH[mt], st + ro);
                ldsm4(aL[mt], st + A_PLANE + ro);
            }
            uint32_t bH[4][2], bL[4][2];
#pragma unroll
            for (int q = 0; q < 2; ++q) {
                const uint32_t ro = (uint32_t)((warp_n * 32 + q * 16 + b_r) * 80 + ks * 32 + b_kb);
                uint32_t t[4];
                ldsm4(t, stB + ro);
                bH[q * 2][0] = t[0]; bH[q * 2][1] = t[1];
                bH[q * 2 + 1][0] = t[2]; bH[q * 2 + 1][1] = t[3];
                ldsm4(t, stB + B_PLANE + ro);
                bL[q * 2][0] = t[0]; bL[q * 2][1] = t[1];
                bL[q * 2 + 1][0] = t[2]; bL[q * 2 + 1][1] = t[3];
            }
#pragma unroll
            for (int mt = 0; mt < 2; ++mt)
#pragma unroll
                for (int nt = 0; nt < 4; ++nt)
                    mma_bf16(acc[mt][nt], aH[mt], bH[nt]);
#pragma unroll
            for (int mt = 0; mt < 2; ++mt)
#pragma unroll
                for (int nt = 0; nt < 4; ++nt)
                    mma_bf16(acc[mt][nt], aH[mt], bL[nt]);
#pragma unroll
            for (int mt = 0; mt < 2; ++mt)
#pragma unroll
                for (int nt = 0; nt < 4; ++nt)
                    mma_bf16(acc[mt][nt], aL[mt], bH[nt]);
        }
        __syncthreads();
    }

    // ------------------------- epilogue -----------------------------------
    const int orow = m0 + warp_m * 32 + (lane >> 2);
    const int ocol = n0 + warp_n * 32 + (lane & 3) * 2;
#pragma unroll
    for (int mt = 0; mt < 2; ++mt) {
#pragma unroll
        for (int nt = 0; nt < 4; ++nt) {
            const int r = orow + mt * 16;
            const int c = ocol + nt * 8;
            float v0 = epi_f<EPI>(acc[mt][nt][0]);
            float v1 = epi_f<EPI>(acc[mt][nt][1]);
            float v2 = epi_f<EPI>(acc[mt][nt][2]);
            float v3 = epi_f<EPI>(acc[mt][nt][3]);
            if (OUTM == 0) {
                float2 u0; u0.x = v0; u0.y = v1;
                float2 u1; u1.x = v2; u1.y = v3;
                *(float2*)&outF[(size_t)r * 256 + c]       = u0;
                *(float2*)&outF[(size_t)(r + 8) * 256 + c] = u1;
            } else {
                __nv_bfloat16 h0, h1, h2, h3, l0, l1, l2, l3;
                split2(v0, h0, l0); split2(v1, h1, l1);
                split2(v2, h2, l2); split2(v3, h3, l3);
                *(__nv_bfloat162*)&outH[(size_t)r * 256 + c]       = __halves2bfloat162(h0, h1);
                *(__nv_bfloat162*)&outH[(size_t)(r + 8) * 256 + c] = __halves2bfloat162(h2, h3);
                *(__nv_bfloat162*)&outL[(size_t)r * 256 + c]       = __halves2bfloat162(l0, l1);
                *(__nv_bfloat162*)&outL[(size_t)(r + 8) * 256 + c] = __halves2bfloat162(l2, l3);
            }
        }
    }
}

// ===========================================================================
// aux kernels
// ===========================================================================
__global__ void split_kernel(const float* __restrict__ in,
                             __nv_bfloat16* __restrict__ hi,
                             __nv_bfloat16* __restrict__ lo, int n4)
{
    int i = blockIdx.x * blockDim.x + threadIdx.x;
    if (i >= n4) return;
    float4 v = ((const float4*)in)[i];
    __nv_bfloat16 h0, h1, h2, h3, l0, l1, l2, l3;
    split2(v.x, h0, l0); split2(v.y, h1, l1); split2(v.z, h2, l2); split2(v.w, h3, l3);
    ((__nv_bfloat162*)hi)[i * 2 + 0] = __halves2bfloat162(h0, h1);
    ((__nv_bfloat162*)hi)[i * 2 + 1] = __halves2bfloat162(h2, h3);
    ((__nv_bfloat162*)lo)[i * 2 + 0] = __halves2bfloat162(l0, l1);
    ((__nv_bfloat162*)lo)[i * 2 + 1] = __halves2bfloat162(l2, l3);
}

// all weights in one launch: 5 x (256x256) + 1 x (512x256)
__global__ void wprep_all(const float* __restrict__ Wq, const float* __restrict__ Wk,
                          const float* __restrict__ Wv, const float* __restrict__ Wm,
                          const float* __restrict__ W2, const float* __restrict__ W1,
                          __nv_bfloat16* __restrict__ dst)
{
    int idx = blockIdx.x * blockDim.x + threadIdx.x;
    const float* W; int K; int within; __nv_bfloat16 *hi, *lo;
    if (idx < 327680) {
        int w = idx >> 16; within = idx & 65535; K = 256;
        const float* srcs[5] = {Wq, Wk, Wv, Wm, W2};
        W = srcs[w];
        int base = (w < 4) ? w * 131072 : 524288;
        hi = dst + base; lo = dst + base + 65536;
    } else if (idx < 458752) {
        within = idx - 327680; K = 512; W = W1;
        hi = dst + 655360; lo = dst + 786432;
    } else return;
    int nn = within / K, kk = within % K;
    split2(W[(size_t)kk * 256 + nn], hi[(size_t)nn * K + kk], lo[(size_t)nn * K + kk]);
}

__global__ void zero_kernel(float* p, int n)
{
    int i = blockIdx.x * blockDim.x + threadIdx.x;
    if (i < n) p[i] = 0.f;
}

__global__ __launch_bounds__(1024) void kv_reduce_kernel(
    const float* __restrict__ Kp, const float* __restrict__ Vp,
    float* __restrict__ KV, float* __restrict__ Ksum, int L)
{
    const int nh = blockIdx.x;
    const int n  = nh >> 3;
    const int h  = nh & 7;
    const int rows = L / gridDim.y;
    const int l0 = blockIdx.y * rows;
    const int tid = threadIdx.x;
    const int d = tid >> 5;
    const int e = tid & 31;

    __shared__ float sk[16][32];
    __shared__ float sv[16][32];

    const size_t base = (size_t)n * L * 256 + h * 32;
    const int ldrow = tid >> 6;
    const int ldc   = tid & 63;

    float acc = 0.f, ks = 0.f;
    for (int l = l0; l < l0 + rows; l += 16) {
        __syncthreads();
        {
            size_t off = base + (size_t)(l + ldrow) * 256;
            if (ldc < 32) sk[ldrow][ldc] = Kp[off + ldc];
            else          sv[ldrow][ldc - 32] = Vp[off + ldc - 32];
        }
        __syncthreads();
#pragma unroll
        for (int r = 0; r < 16; ++r) acc += sk[r][d] * sv[r][e];
        if (e == 0) {
#pragma unroll
            for (int r = 0; r < 16; ++r) ks += sk[r][d];
        }
    }
    atomicAdd(&KV[(size_t)nh * 1024 + d * 32 + e], acc);
    if (e == 0) atomicAdd(&Ksum[nh * 32 + d], ks);
}

__global__ __launch_bounds__(256) void msg_kernel(
    const float* __restrict__ Q, const float* __restrict__ KV,
    const float* __restrict__ Ksum,
    __nv_bfloat16* __restrict__ MH, __nv_bfloat16* __restrict__ ML, int L)
{
    const int row = blockIdx.x;
    const int n = row / L;
    const int tid = threadIdx.x;
    const int h = tid >> 5;
    const int e = tid & 31;

    __shared__ float qs[256];
    qs[tid] = Q[(size_t)row * 256 + tid];
    __syncthreads();

    float p = qs[h * 32 + e] * Ksum[(n * 8 + h) * 32 + e];
#pragma unroll
    for (int o = 16; o; o >>= 1) p += __shfl_xor_sync(0xffffffffu, p, o);
    const float z = 1.f / (p + 1e-6f);

    const float* kv = KV + (size_t)(n * 8 + h) * 1024;
    float acc = 0.f;
#pragma unroll
    for (int dd = 0; dd < 32; ++dd) acc += qs[h * 32 + dd] * kv[dd * 32 + e];

    split2(acc * z, MH[(size_t)row * 256 + tid], ML[(size_t)row * 256 + tid]);
}

template <int OUT>
__global__ __launch_bounds__(256) void ln_kernel(
    const float* __restrict__ in, const float* __restrict__ res,
    const float* __restrict__ g, const float* __restrict__ b,
    float* __restrict__ outf,
    __nv_bfloat16* __restrict__ oh, __nv_bfloat16* __restrict__ ol, int rows)
{
    const int gw = (int)((blockIdx.x * blockDim.x + threadIdx.x) >> 5);
    if (gw >= rows) return;
    const int lane = threadIdx.x & 31;

    const float4* rp = (const float4*)(in + (size_t)gw * 256);
    float v[8];
    *(float4*)&v[0] = rp[lane];
    *(float4*)&v[4] = rp[lane + 32];

    float s = 0.f;
#pragma unroll
    for (int i = 0; i < 8; ++i) s += v[i];
#pragma unroll
    for (int o = 16; o; o >>= 1) s += __shfl_xor_sync(0xffffffffu, s, o);
    const float mu = s * (1.f / 256.f);

    float vs = 0.f;
#pragma unroll
    for (int i = 0; i < 8; ++i) { v[i] -= mu; vs += v[i] * v[i]; }
#pragma unroll
    for (int o = 16; o; o >>= 1) vs += __shfl_xor_sync(0xffffffffu, vs, o);
    const float rstd = rsqrtf(vs * (1.f / 256.f) + 1e-5f);

    float G[8], Bv[8];
    *(float4*)&G[0]  = ((const float4*)g)[lane];
    *(float4*)&G[4]  = ((const float4*)g)[lane + 32];
    *(float4*)&Bv[0] = ((const float4*)b)[lane];
    *(float4*)&Bv[4] = ((const float4*)b)[lane + 32];

    float o8[8];
#pragma unroll
    for (int i = 0; i < 8; ++i) o8[i] = v[i] * rstd * G[i] + Bv[i];

    if (OUT == 0) {
        if (res) {
            const float4* xp = (const float4*)(res + (size_t)gw * 256);
            float r8[8];
            *(float4*)&r8[0] = xp[lane];
            *(float4*)&r8[4] = xp[lane + 32];
#pragma unroll
            for (int i = 0; i < 8; ++i) o8[i] += r8[i];
        }
        float4* op = (float4*)(outf + (size_t)gw * 256);
        op[lane]      = *(float4*)&o8[0];
        op[lane + 32] = *(float4*)&o8[4];
    } else {
        __nv_bfloat16 h[8], l[8];
#pragma unroll
        for (int i = 0; i < 8; ++i) split2(o8[i], h[i], l[i]);
        __nv_bfloat162* ph0 = (__nv_bfloat162*)(oh + (size_t)gw * 256 + lane * 4);
        __nv_bfloat162* ph1 = (__nv_bfloat162*)(oh + (size_t)gw * 256 + 128 + lane * 4);
        __nv_bfloat162* pl0 = (__nv_bfloat162*)(ol + (size_t)gw * 256 + lane * 4);
        __nv_bfloat162* pl1 = (__nv_bfloat162*)(ol + (size_t)gw * 256 + 128 + lane * 4);
        ph0[0] = __halves2bfloat162(h[0], h[1]); ph0[1] = __halves2bfloat162(h[2], h[3]);
        ph1[0] = __halves2bfloat162(h[4], h[5]); ph1[1] = __halves2bfloat162(h[6], h[7]);
        pl0[0] = __halves2bfloat162(l[0], l[1]); pl0[1] = __halves2bfloat162(l[2], l[3]);
        pl1[0] = __halves2bfloat162(l[4], l[5]); pl1[1] = __halves2bfloat162(l[6], l[7]);
    }
}

// ===========================================================================
// launch
// ===========================================================================
extern "C" void kernel_launch(void* const* d_in, const int* in_sizes, int n_in,
                              void* d_out, int out_size)
{
    const float* x  = (const float*)d_in[0];
    const float* Wq = (const float*)d_in[1];
    const float* Wk = (const float*)d_in[2];
    const float* Wv = (const float*)d_in[3];
    const float* Wm = (const float*)d_in[4];
    const float* W1 = (const float*)d_in[5];
    const float* W2 = (const float*)d_in[6];
    const float* g1 = (const float*)d_in[7];
    const float* b1 = (const float*)d_in[8];
    const float* g2 = (const float*)d_in[9];
    const float* b2 = (const float*)d_in[10];

    const int M = in_sizes[0] / C_DIM;   // 65536
    const int L = M / NB;                // 16384

    float *Qf, *Kf, *Vf, *sm;
    __nv_bfloat16 *xhi, *xlo, *mhi, *mlo, *lhi, *llo, *hhi, *hlo, *gw;
    cudaGetSymbolAddress((void**)&Qf, g_Q);
    cudaGetSymbolAddress((void**)&Kf, g_K);
    cudaGetSymbolAddress((void**)&Vf, g_V);
    cudaGetSymbolAddress((void**)&xhi, g_xhi);
    cudaGetSymbolAddress((void**)&xlo, g_xlo);
    cudaGetSymbolAddress((void**)&mhi, g_mhi);
    cudaGetSymbolAddress((void**)&mlo, g_mlo);
    cudaGetSymbolAddress((void**)&lhi, g_lhi);
    cudaGetSymbolAddress((void**)&llo, g_llo);
    cudaGetSymbolAddress((void**)&hhi, g_hhi);
    cudaGetSymbolAddress((void**)&hlo, g_hlo);
    cudaGetSymbolAddress((void**)&gw, g_w);
    cudaGetSymbolAddress((void**)&sm, g_small);
    float* KV   = sm;
    float* Ksum = sm + 32 * 1024;

    __nv_bfloat16 *wqh = gw,           *wql = gw + 65536;
    __nv_bfloat16 *wkh = gw + 131072,  *wkl = gw + 196608;
    __nv_bfloat16 *wvh = gw + 262144,  *wvl = gw + 327680;
    __nv_bfloat16 *wmh = gw + 393216,  *wml = gw + 458752;
    __nv_bfloat16 *w2h = gw + 524288,  *w2l = gw + 589824;
    __nv_bfloat16 *w1h = gw + 655360,  *w1l = gw + 786432;

    cudaFuncSetAttribute(gemm_mma<256, 1, 0>, cudaFuncAttributeMaxDynamicSharedMemorySize, GEMM_SMEM);
    cudaFuncSetAttribute(gemm_mma<256, 0, 0>, cudaFuncAttributeMaxDynamicSharedMemorySize, GEMM_SMEM);
    cudaFuncSetAttribute(gemm_mma<512, 2, 1>, cudaFuncAttributeMaxDynamicSharedMemorySize, GEMM_SMEM);

    wprep_all<<<(458752 + 255) / 256, 256>>>(Wq, Wk, Wv, Wm, W2, W1, gw);
    split_kernel<<<(M * 64 + 255) / 256, 256>>>(x, xhi, xlo, M * 64);

    dim3 gg(4, M / 128);   // (N tiles of 64, M tiles of 128)

    gemm_mma<256, 1, 0><<<gg, 256, GEMM_SMEM>>>(xhi, xlo, nullptr, nullptr, wqh, wql, Qf, nullptr, nullptr);
    gemm_mma<256, 1, 0><<<gg, 256, GEMM_SMEM>>>(xhi, xlo, nullptr, nullptr, wkh, wkl, Kf, nullptr, nullptr);
    gemm_mma<256, 0, 0><<<gg, 256, GEMM_SMEM>>>(xhi, xlo, nullptr, nullptr, wvh, wvl, Vf, nullptr, nullptr);

    zero_kernel<<<(33792 + 255) / 256, 256>>>(sm, 33792);
    kv_reduce_kernel<<<dim3(32, 64), 1024>>>(Kf, Vf, KV, Ksum, L);

    msg_kernel<<<M, 256>>>(Qf, KV, Ksum, mhi, mlo, L);

    gemm_mma<256, 0, 0><<<gg, 256, GEMM_SMEM>>>(mhi, mlo, nullptr, nullptr, wmh, wml, Kf, nullptr, nullptr);
    ln_kernel<1><<<M / 8, 256>>>(Kf, nullptr, g1, b1, nullptr, lhi, llo, M);

    gemm_mma<512, 2, 1><<<gg, 256, GEMM_SMEM>>>(xhi, xlo, lhi, llo, w1h, w1l, nullptr, hhi, hlo);

    gemm_mma<256, 0, 0><<<gg, 256, GEMM_SMEM>>>(hhi, hlo, nullptr, nullptr, w2h, w2l, Vf, nullptr, nullptr);
    ln_kernel<0><<<M / 8, 256>>>(Vf, x, g2, b2, (float*)d_out, nullptr, nullptr, M);
}

// round 7
// speedup vs baseline: 1.0003x; 1.0003x over previous
#include <cuda_runtime.h>
#include <cuda_bf16.h>
#include <cstdint>
#include <cstddef>

// ===========================================================================
// StructureAttention, mma.sync bf16 hi/lo x3, fp32 accum.
// R6: R5 design (128x64 tile, 3x30KB stages, 2 CTAs/SM) with loader OOB fix
// (4 chunks of 16B per 64B row; padding never written/read).
// ===========================================================================

#define C_DIM 256
#define NB    4
#define MTOT  16777216

__device__ float g_Q[MTOT];
__device__ float g_K[MTOT];
__device__ float g_V[MTOT];
__device__ __nv_bfloat16 g_xhi[MTOT], g_xlo[MTOT];
__device__ __nv_bfloat16 g_mhi[MTOT], g_mlo[MTOT];
__device__ __nv_bfloat16 g_lhi[MTOT], g_llo[MTOT];
__device__ __nv_bfloat16 g_hhi[MTOT], g_hlo[MTOT];
__device__ __nv_bfloat16 g_w[917504];
__device__ float g_small[32 * 1024 + 32 * 32];

// ---------------- helpers --------------------------------------------------
__device__ __forceinline__ uint32_t smem_u32(const void* p) {
    uint32_t a;
    asm("{ .reg .u64 t; cvta.to.shared.u64 t, %1; cvt.u32.u64 %0, t; }" : "=r"(a) : "l"(p));
    return a;
}
__device__ __forceinline__ void cp16(uint32_t dst, const void* src) {
    asm volatile("cp.async.cg.shared.global [%0], [%1], 16;"
                 :: "r"(dst), "l"(__cvta_generic_to_global(src)) : "memory");
}
#define CP_COMMIT() asm volatile("cp.async.commit_group;" ::: "memory")
#define CP_WAIT1()  asm volatile("cp.async.wait_group 1;"  ::: "memory")

__device__ __forceinline__ void ldsm4(uint32_t* r, uint32_t addr) {
    asm volatile("ldmatrix.sync.aligned.m8n8.x4.shared.b16 {%0,%1,%2,%3}, [%4];"
                 : "=r"(r[0]), "=r"(r[1]), "=r"(r[2]), "=r"(r[3]) : "r"(addr));
}
__device__ __forceinline__ void mma_bf16(float* c, const uint32_t* a, const uint32_t* b) {
    asm("mma.sync.aligned.m16n8k16.row.col.f32.bf16.bf16.f32 "
        "{%0,%1,%2,%3}, {%4,%5,%6,%7}, {%8,%9}, {%0,%1,%2,%3};"
        : "+f"(c[0]), "+f"(c[1]), "+f"(c[2]), "+f"(c[3])
        : "r"(a[0]), "r"(a[1]), "r"(a[2]), "r"(a[3]), "r"(b[0]), "r"(b[1]));
}
__device__ __forceinline__ void split2(float v, __nv_bfloat16& hi, __nv_bfloat16& lo) {
    hi = __float2bfloat16(v);
    lo = __float2bfloat16(v - __bfloat162float(hi));
}
template <int EPI>
__device__ __forceinline__ float epi_f(float t) {
    if (EPI == 1) return t > 0.f ? t + 1.f : __expf(t);   // phi = elu+1
    if (EPI == 2) return fmaxf(t, 0.f);                   // relu
    return t;
}

// ===========================================================================
// HMMA GEMM: out[M,256] = A[M,KDIM] * W[KDIM,256]; W transposed
// (Wt[256,KDIM]) as bf16 hi/lo planes; A as bf16 hi/lo planes (row len 256;
// KDIM=512 -> second plane pair = cols 256..511).
// CTA 128x64, BK=32, 3-stage cp.async (30KB/stage), 8 warps (4x2),
// warp tile 32x32, 2 CTAs/SM.  acc += Ah*Wh + Ah*Wl + Al*Wh.
// ===========================================================================
#define A_PLANE   10240           // 128 rows * 80B
#define B_PLANE   5120            // 64 rows * 80B
#define STAGE_B   30720           // 2*A_PLANE + 2*B_PLANE
#define GEMM_SMEM (3 * STAGE_B)   // 92160

template <int KDIM, int EPI, int OUTM>
__global__ __launch_bounds__(256, 2)
void gemm_mma(const __nv_bfloat16* __restrict__ A0h, const __nv_bfloat16* __restrict__ A0l,
              const __nv_bfloat16* __restrict__ A1h, const __nv_bfloat16* __restrict__ A1l,
              const __nv_bfloat16* __restrict__ Bh,  const __nv_bfloat16* __restrict__ Bl,
              float* __restrict__ outF,
              __nv_bfloat16* __restrict__ outH, __nv_bfloat16* __restrict__ outL)
{
    extern __shared__ char dsm[];
    const uint32_t sb = smem_u32(dsm);

    const int tid    = threadIdx.x;
    const int lane   = tid & 31;
    const int wid    = tid >> 5;
    const int warp_m = wid >> 1;          // 0..3 (32 rows each)
    const int warp_n = wid & 1;           // 0..1 (32 cols each)
    const int n0     = blockIdx.x * 64;
    const int m0     = blockIdx.y * 128;
    constexpr int NIT = KDIM / 32;

    // loader mapping: A: 256 threads -> 2 planes x 128 rows, 4x16B per row.
    const int a_pl  = tid >> 7;           // 0..1
    const int a_row = tid & 127;
    // B: threads 0..127 -> 2 planes x 64 rows, 4x16B per row.
    const int b_pl  = (tid & 127) >> 6;
    const int b_row = tid & 63;
    const bool b_act = tid < 128;

    float acc[2][4][4];
#pragma unroll
    for (int mt = 0; mt < 2; ++mt)
#pragma unroll
        for (int nt = 0; nt < 4; ++nt)
#pragma unroll
            for (int q = 0; q < 4; ++q) acc[mt][nt][q] = 0.f;

    auto load_stage = [&](int buf, int it) {
        const uint32_t st = sb + buf * STAGE_B;
        const int kc = it * 32;
        const __nv_bfloat16 *Ah, *Al;
        int kk = kc;
        if (KDIM == 512 && kc >= 256) { Ah = A1h; Al = A1l; kk = kc - 256; }
        else                          { Ah = A0h; Al = A0l; }
        {
            const __nv_bfloat16* ap = a_pl ? Al : Ah;
            const __nv_bfloat16* srow = ap + (size_t)(m0 + a_row) * 256 + kk;
            const uint32_t drow = st + a_pl * A_PLANE + a_row * 80;
#pragma unroll
            for (int j = 0; j < 4; ++j) cp16(drow + j * 16, srow + j * 8);
        }
        if (b_act) {
            const __nv_bfloat16* bp = b_pl ? Bl : Bh;
            const __nv_bfloat16* srow = bp + (size_t)(n0 + b_row) * KDIM + kc;
            const uint32_t drow = st + 2 * A_PLANE + b_pl * B_PLANE + b_row * 80;
#pragma unroll
            for (int j = 0; j < 4; ++j) cp16(drow + j * 16, srow + j * 8);
        }
    };

    load_stage(0, 0); CP_COMMIT();
    load_stage(1, 1); CP_COMMIT();

    const int g  = lane >> 3;
    const int li = lane & 7;
    const int a_r  = li + (g & 1) * 8;
    const int a_kb = (g >> 1) * 16;
    const int b_r  = li + (g >> 1) * 8;
    const int b_kb = (g & 1) * 16;

    for (int it = 0; it < NIT; ++it) {
        CP_WAIT1();
        __syncthreads();
        if (it + 2 < NIT) load_stage((it + 2) % 3, it + 2);
        CP_COMMIT();

        const uint32_t st  = sb + (it % 3) * STAGE_B;
        const uint32_t stB = st + 2 * A_PLANE;

#pragma unroll
        for (int ks = 0; ks < 2; ++ks) {
            uint32_t aH[2][4], aL[2][4];
#pragma unroll
            for (int mt = 0; mt < 2; ++mt) {
                const uint32_t ro = (uint32_t)((warp_m * 32 + mt * 16 + a_r) * 80 + ks * 32 + a_kb);
                ldsm4(aH[mt], st + ro);
                ldsm4(aL[mt], st + A_PLANE + ro);
            }
            uint32_t bH[4][2], bL[4][2];
#pragma unroll
            for (int q = 0; q < 2; ++q) {
                const uint32_t ro = (uint32_t)((warp_n * 32 + q * 16 + b_r) * 80 + ks * 32 + b_kb);
                uint32_t t[4];
                ldsm4(t, stB + ro);
                bH[q * 2][0] = t[0]; bH[q * 2][1] = t[1];
                bH[q * 2 + 1][0] = t[2]; bH[q * 2 + 1][1] = t[3];
                ldsm4(t, stB + B_PLANE + ro);
                bL[q * 2][0] = t[0]; bL[q * 2][1] = t[1];
                bL[q * 2 + 1][0] = t[2]; bL[q * 2 + 1][1] = t[3];
            }
#pragma unroll
            for (int mt = 0; mt < 2; ++mt)
#pragma unroll
                for (int nt = 0; nt < 4; ++nt)
                    mma_bf16(acc[mt][nt], aH[mt], bH[nt]);
#pragma unroll
            for (int mt = 0; mt < 2; ++mt)
#pragma unroll
                for (int nt = 0; nt < 4; ++nt)
                    mma_bf16(acc[mt][nt], aH[mt], bL[nt]);
#pragma unroll
            for (int mt = 0; mt < 2; ++mt)
#pragma unroll
                for (int nt = 0; nt < 4; ++nt)
                    mma_bf16(acc[mt][nt], aL[mt], bH[nt]);
        }
        __syncthreads();
    }

    // ------------------------- epilogue -----------------------------------
    const int orow = m0 + warp_m * 32 + (lane >> 2);
    const int ocol = n0 + warp_n * 32 + (lane & 3) * 2;
#pragma unroll
    for (int mt = 0; mt < 2; ++mt) {
#pragma unroll
        for (int nt = 0; nt < 4; ++nt) {
            const int r = orow + mt * 16;
            const int c = ocol + nt * 8;
            float v0 = epi_f<EPI>(acc[mt][nt][0]);
            float v1 = epi_f<EPI>(acc[mt][nt][1]);
            float v2 = epi_f<EPI>(acc[mt][nt][2]);
            float v3 = epi_f<EPI>(acc[mt][nt][3]);
            if (OUTM == 0) {
                float2 u0; u0.x = v0; u0.y = v1;
                float2 u1; u1.x = v2; u1.y = v3;
                *(float2*)&outF[(size_t)r * 256 + c]       = u0;
                *(float2*)&outF[(size_t)(r + 8) * 256 + c] = u1;
            } else {
                __nv_bfloat16 h0, h1, h2, h3, l0, l1, l2, l3;
                split2(v0, h0, l0); split2(v1, h1, l1);
                split2(v2, h2, l2); split2(v3, h3, l3);
                *(__nv_bfloat162*)&outH[(size_t)r * 256 + c]       = __halves2bfloat162(h0, h1);
                *(__nv_bfloat162*)&outH[(size_t)(r + 8) * 256 + c] = __halves2bfloat162(h2, h3);
                *(__nv_bfloat162*)&outL[(size_t)r * 256 + c]       = __halves2bfloat162(l0, l1);
                *(__nv_bfloat162*)&outL[(size_t)(r + 8) * 256 + c] = __halves2bfloat162(l2, l3);
            }
        }
    }
}

// ===========================================================================
// aux kernels
// ===========================================================================
__global__ void split_kernel(const float* __restrict__ in,
                             __nv_bfloat16* __restrict__ hi,
                             __nv_bfloat16* __restrict__ lo, int n4)
{
    int i = blockIdx.x * blockDim.x + threadIdx.x;
    if (i >= n4) return;
    float4 v = ((const float4*)in)[i];
    __nv_bfloat16 h0, h1, h2, h3, l0, l1, l2, l3;
    split2(v.x, h0, l0); split2(v.y, h1, l1); split2(v.z, h2, l2); split2(v.w, h3, l3);
    ((__nv_bfloat162*)hi)[i * 2 + 0] = __halves2bfloat162(h0, h1);
    ((__nv_bfloat162*)hi)[i * 2 + 1] = __halves2bfloat162(h2, h3);
    ((__nv_bfloat162*)lo)[i * 2 + 0] = __halves2bfloat162(l0, l1);
    ((__nv_bfloat162*)lo)[i * 2 + 1] = __halves2bfloat162(l2, l3);
}

// all weights in one launch: 5 x (256x256) + 1 x (512x256)
__global__ void wprep_all(const float* __restrict__ Wq, const float* __restrict__ Wk,
                          const float* __restrict__ Wv, const float* __restrict__ Wm,
                          const float* __restrict__ W2, const float* __restrict__ W1,
                          __nv_bfloat16* __restrict__ dst)
{
    int idx = blockIdx.x * blockDim.x + threadIdx.x;
    const float* W; int K; int within; __nv_bfloat16 *hi, *lo;
    if (idx < 327680) {
        int w = idx >> 16; within = idx & 65535; K = 256;
        const float* srcs[5] = {Wq, Wk, Wv, Wm, W2};
        W = srcs[w];
        int base = (w < 4) ? w * 131072 : 524288;
        hi = dst + base; lo = dst + base + 65536;
    } else if (idx < 458752) {
        within = idx - 327680; K = 512; W = W1;
        hi = dst + 655360; lo = dst + 786432;
    } else return;
    int nn = within / K, kk = within % K;
    split2(W[(size_t)kk * 256 + nn], hi[(size_t)nn * K + kk], lo[(size_t)nn * K + kk]);
}

__global__ void zero_kernel(float* p, int n)
{
    int i = blockIdx.x * blockDim.x + threadIdx.x;
    if (i < n) p[i] = 0.f;
}

__global__ __launch_bounds__(1024) void kv_reduce_kernel(
    const float* __restrict__ Kp, const float* __restrict__ Vp,
    float* __restrict__ KV, float* __restrict__ Ksum, int L)
{
    const int nh = blockIdx.x;
    const int n  = nh >> 3;
    const int h  = nh & 7;
    const int rows = L / gridDim.y;
    const int l0 = blockIdx.y * rows;
    const int tid = threadIdx.x;
    const int d = tid >> 5;
    const int e = tid & 31;

    __shared__ float sk[16][32];
    __shared__ float sv[16][32];

    const size_t base = (size_t)n * L * 256 + h * 32;
    const int ldrow = tid >> 6;
    const int ldc   = tid & 63;

    float acc = 0.f, ks = 0.f;
    for (int l = l0; l < l0 + rows; l += 16) {
        __syncthreads();
        {
            size_t off = base + (size_t)(l + ldrow) * 256;
            if (ldc < 32) sk[ldrow][ldc] = Kp[off + ldc];
            else          sv[ldrow][ldc - 32] = Vp[off + ldc - 32];
        }
        __syncthreads();
#pragma unroll
        for (int r = 0; r < 16; ++r) acc += sk[r][d] * sv[r][e];
        if (e == 0) {
#pragma unroll
            for (int r = 0; r < 16; ++r) ks += sk[r][d];
        }
    }
    atomicAdd(&KV[(size_t)nh * 1024 + d * 32 + e], acc);
    if (e == 0) atomicAdd(&Ksum[nh * 32 + d], ks);
}

__global__ __launch_bounds__(256) void msg_kernel(
    const float* __restrict__ Q, const float* __restrict__ KV,
    const float* __restrict__ Ksum,
    __nv_bfloat16* __restrict__ MH, __nv_bfloat16* __restrict__ ML, int L)
{
    const int row = blockIdx.x;
    const int n = row / L;
    const int tid = threadIdx.x;
    const int h = tid >> 5;
    const int e = tid & 31;

    __shared__ float qs[256];
    qs[tid] = Q[(size_t)row * 256 + tid];
    __syncthreads();

    float p = qs[h * 32 + e] * Ksum[(n * 8 + h) * 32 + e];
#pragma unroll
    for (int o = 16; o; o >>= 1) p += __shfl_xor_sync(0xffffffffu, p, o);
    const float z = 1.f / (p + 1e-6f);

    const float* kv = KV + (size_t)(n * 8 + h) * 1024;
    float acc = 0.f;
#pragma unroll
    for (int dd = 0; dd < 32; ++dd) acc += qs[h * 32 + dd] * kv[dd * 32 + e];

    split2(acc * z, MH[(size_t)row * 256 + tid], ML[(size_t)row * 256 + tid]);
}

template <int OUT>
__global__ __launch_bounds__(256) void ln_kernel(
    const float* __restrict__ in, const float* __restrict__ res,
    const float* __restrict__ g, const float* __restrict__ b,
    float* __restrict__ outf,
    __nv_bfloat16* __restrict__ oh, __nv_bfloat16* __restrict__ ol, int rows)
{
    const int gw = (int)((blockIdx.x * blockDim.x + threadIdx.x) >> 5);
    if (gw >= rows) return;
    const int lane = threadIdx.x & 31;

    const float4* rp = (const float4*)(in + (size_t)gw * 256);
    float v[8];
    *(float4*)&v[0] = rp[lane];
    *(float4*)&v[4] = rp[lane + 32];

    float s = 0.f;
#pragma unroll
    for (int i = 0; i < 8; ++i) s += v[i];
#pragma unroll
    for (int o = 16; o; o >>= 1) s += __shfl_xor_sync(0xffffffffu, s, o);
    const float mu = s * (1.f / 256.f);

    float vs = 0.f;
#pragma unroll
    for (int i = 0; i < 8; ++i) { v[i] -= mu; vs += v[i] * v[i]; }
#pragma unroll
    for (int o = 16; o; o >>= 1) vs += __shfl_xor_sync(0xffffffffu, vs, o);
    const float rstd = rsqrtf(vs * (1.f / 256.f) + 1e-5f);

    float G[8], Bv[8];
    *(float4*)&G[0]  = ((const float4*)g)[lane];
    *(float4*)&G[4]  = ((const float4*)g)[lane + 32];
    *(float4*)&Bv[0] = ((const float4*)b)[lane];
    *(float4*)&Bv[4] = ((const float4*)b)[lane + 32];

    float o8[8];
#pragma unroll
    for (int i = 0; i < 8; ++i) o8[i] = v[i] * rstd * G[i] + Bv[i];

    if (OUT == 0) {
        if (res) {
            const float4* xp = (const float4*)(res + (size_t)gw * 256);
            float r8[8];
            *(float4*)&r8[0] = xp[lane];
            *(float4*)&r8[4] = xp[lane + 32];
#pragma unroll
            for (int i = 0; i < 8; ++i) o8[i] += r8[i];
        }
        float4* op = (float4*)(outf + (size_t)gw * 256);
        op[lane]      = *(float4*)&o8[0];
        op[lane + 32] = *(float4*)&o8[4];
    } else {
        __nv_bfloat16 h[8], l[8];
#pragma unroll
        for (int i = 0; i < 8; ++i) split2(o8[i], h[i], l[i]);
        __nv_bfloat162* ph0 = (__nv_bfloat162*)(oh + (size_t)gw * 256 + lane * 4);
        __nv_bfloat162* ph1 = (__nv_bfloat162*)(oh + (size_t)gw * 256 + 128 + lane * 4);
        __nv_bfloat162* pl0 = (__nv_bfloat162*)(ol + (size_t)gw * 256 + lane * 4);
        __nv_bfloat162* pl1 = (__nv_bfloat162*)(ol + (size_t)gw * 256 + 128 + lane * 4);
        ph0[0] = __halves2bfloat162(h[0], h[1]); ph0[1] = __halves2bfloat162(h[2], h[3]);
        ph1[0] = __halves2bfloat162(h[4], h[5]); ph1[1] = __halves2bfloat162(h[6], h[7]);
        pl0[0] = __halves2bfloat162(l[0], l[1]); pl0[1] = __halves2bfloat162(l[2], l[3]);
        pl1[0] = __halves2bfloat162(l[4], l[5]); pl1[1] = __halves2bfloat162(l[6], l[7]);
    }
}

// ===========================================================================
// launch
// ===========================================================================
extern "C" void kernel_launch(void* const* d_in, const int* in_sizes, int n_in,
                              void* d_out, int out_size)
{
    const float* x  = (const float*)d_in[0];
    const float* Wq = (const float*)d_in[1];
    const float* Wk = (const float*)d_in[2];
    const float* Wv = (const float*)d_in[3];
    const float* Wm = (const float*)d_in[4];
    const float* W1 = (const float*)d_in[5];
    const float* W2 = (const float*)d_in[6];
    const float* g1 = (const float*)d_in[7];
    const float* b1 = (const float*)d_in[8];
    const float* g2 = (const float*)d_in[9];
    const float* b2 = (const float*)d_in[10];

    const int M = in_sizes[0] / C_DIM;   // 65536
    const int L = M / NB;                // 16384

    float *Qf, *Kf, *Vf, *sm;
    __nv_bfloat16 *xhi, *xlo, *mhi, *mlo, *lhi, *llo, *hhi, *hlo, *gw;
    cudaGetSymbolAddress((void**)&Qf, g_Q);
    cudaGetSymbolAddress((void**)&Kf, g_K);
    cudaGetSymbolAddress((void**)&Vf, g_V);
    cudaGetSymbolAddress((void**)&xhi, g_xhi);
    cudaGetSymbolAddress((void**)&xlo, g_xlo);
    cudaGetSymbolAddress((void**)&mhi, g_mhi);
    cudaGetSymbolAddress((void**)&mlo, g_mlo);
    cudaGetSymbolAddress((void**)&lhi, g_lhi);
    cudaGetSymbolAddress((void**)&llo, g_llo);
    cudaGetSymbolAddress((void**)&hhi, g_hhi);
    cudaGetSymbolAddress((void**)&hlo, g_hlo);
    cudaGetSymbolAddress((void**)&gw, g_w);
    cudaGetSymbolAddress((void**)&sm, g_small);
    float* KV   = sm;
    float* Ksum = sm + 32 * 1024;

    __nv_bfloat16 *wqh = gw,           *wql = gw + 65536;
    __nv_bfloat16 *wkh = gw + 131072,  *wkl = gw + 196608;
    __nv_bfloat16 *wvh = gw + 262144,  *wvl = gw + 327680;
    __nv_bfloat16 *wmh = gw + 393216,  *wml = gw + 458752;
    __nv_bfloat16 *w2h = gw + 524288,  *w2l = gw + 589824;
    __nv_bfloat16 *w1h = gw + 655360,  *w1l = gw + 786432;

    cudaFuncSetAttribute(gemm_mma<256, 1, 0>, cudaFuncAttributeMaxDynamicSharedMemorySize, GEMM_SMEM);
    cudaFuncSetAttribute(gemm_mma<256, 0, 0>, cudaFuncAttributeMaxDynamicSharedMemorySize, GEMM_SMEM);
    cudaFuncSetAttribute(gemm_mma<512, 2, 1>, cudaFuncAttributeMaxDynamicSharedMemorySize, GEMM_SMEM);

    wprep_all<<<(458752 + 255) / 256, 256>>>(Wq, Wk, Wv, Wm, W2, W1, gw);
    split_kernel<<<(M * 64 + 255) / 256, 256>>>(x, xhi, xlo, M * 64);

    dim3 gg(4, M / 128);   // (N tiles of 64, M tiles of 128)

    gemm_mma<256, 1, 0><<<gg, 256, GEMM_SMEM>>>(xhi, xlo, nullptr, nullptr, wqh, wql, Qf, nullptr, nullptr);
    gemm_mma<256, 1, 0><<<gg, 256, GEMM_SMEM>>>(xhi, xlo, nullptr, nullptr, wkh, wkl, Kf, nullptr, nullptr);
    gemm_mma<256, 0, 0><<<gg, 256, GEMM_SMEM>>>(xhi, xlo, nullptr, nullptr, wvh, wvl, Vf, nullptr, nullptr);

    zero_kernel<<<(33792 + 255) / 256, 256>>>(sm, 33792);
    kv_reduce_kernel<<<dim3(32, 64), 1024>>>(Kf, Vf, KV, Ksum, L);

    msg_kernel<<<M, 256>>>(Qf, KV, Ksum, mhi, mlo, L);

    gemm_mma<256, 0, 0><<<gg, 256, GEMM_SMEM>>>(mhi, mlo, nullptr, nullptr, wmh, wml, Kf, nullptr, nullptr);
    ln_kernel<1><<<M / 8, 256>>>(Kf, nullptr, g1, b1, nullptr, lhi, llo, M);

    gemm_mma<512, 2, 1><<<gg, 256, GEMM_SMEM>>>(xhi, xlo, lhi, llo, w1h, w1l, nullptr, hhi, hlo);

    gemm_mma<256, 0, 0><<<gg, 256, GEMM_SMEM>>>(hhi, hlo, nullptr, nullptr, w2h, w2l, Vf, nullptr, nullptr);
    ln_kernel<0><<<M / 8, 256>>>(Vf, x, g2, b2, (float*)d_out, nullptr, nullptr, M);
}

// round 8
// speedup vs baseline: 1.0240x; 1.0238x over previous
#include <cuda_runtime.h>
#include <cuda_bf16.h>
#include <cstdint>
#include <cstddef>

// ===========================================================================
// StructureAttention, mma.sync bf16 hi/lo x3, fp32 accum.
// R8: CTA tile 128x256 (full N) -> A read once (L2 traffic halved);
// warp tile 64x64 -> 6 MMA per LDSM.x4; 3-stage x 60KB; 1 CTA/SM.
// ===========================================================================

#define C_DIM 256
#define NB    4
#define MTOT  16777216

__device__ float g_Q[MTOT];
__device__ float g_K[MTOT];
__device__ float g_V[MTOT];
__device__ __nv_bfloat16 g_xhi[MTOT], g_xlo[MTOT];
__device__ __nv_bfloat16 g_mhi[MTOT], g_mlo[MTOT];
__device__ __nv_bfloat16 g_lhi[MTOT], g_llo[MTOT];
__device__ __nv_bfloat16 g_hhi[MTOT], g_hlo[MTOT];
__device__ __nv_bfloat16 g_w[917504];
__device__ float g_small[32 * 1024 + 32 * 32];

// ---------------- helpers --------------------------------------------------
__device__ __forceinline__ uint32_t smem_u32(const void* p) {
    uint32_t a;
    asm("{ .reg .u64 t; cvta.to.shared.u64 t, %1; cvt.u32.u64 %0, t; }" : "=r"(a) : "l"(p));
    return a;
}
__device__ __forceinline__ void cp16(uint32_t dst, const void* src) {
    asm volatile("cp.async.cg.shared.global [%0], [%1], 16;"
                 :: "r"(dst), "l"(__cvta_generic_to_global(src)) : "memory");
}
#define CP_COMMIT() asm volatile("cp.async.commit_group;" ::: "memory")
#define CP_WAIT1()  asm volatile("cp.async.wait_group 1;"  ::: "memory")

__device__ __forceinline__ void ldsm4(uint32_t* r, uint32_t addr) {
    asm volatile("ldmatrix.sync.aligned.m8n8.x4.shared.b16 {%0,%1,%2,%3}, [%4];"
                 : "=r"(r[0]), "=r"(r[1]), "=r"(r[2]), "=r"(r[3]) : "r"(addr));
}
__device__ __forceinline__ void mma_bf16(float* c, const uint32_t* a, const uint32_t* b) {
    asm("mma.sync.aligned.m16n8k16.row.col.f32.bf16.bf16.f32 "
        "{%0,%1,%2,%3}, {%4,%5,%6,%7}, {%8,%9}, {%0,%1,%2,%3};"
        : "+f"(c[0]), "+f"(c[1]), "+f"(c[2]), "+f"(c[3])
        : "r"(a[0]), "r"(a[1]), "r"(a[2]), "r"(a[3]), "r"(b[0]), "r"(b[1]));
}
__device__ __forceinline__ void split2(float v, __nv_bfloat16& hi, __nv_bfloat16& lo) {
    hi = __float2bfloat16(v);
    lo = __float2bfloat16(v - __bfloat162float(hi));
}
template <int EPI>
__device__ __forceinline__ float epi_f(float t) {
    if (EPI == 1) return t > 0.f ? t + 1.f : __expf(t);   // phi = elu+1
    if (EPI == 2) return fmaxf(t, 0.f);                   // relu
    return t;
}

// ===========================================================================
// HMMA GEMM: out[M,256] = A[M,KDIM] * W[KDIM,256]; W transposed
// (Wt[256,KDIM]) as bf16 hi/lo planes; A as bf16 hi/lo planes (row len 256;
// KDIM=512 -> second plane pair = cols 256..511).
// CTA 128x256 (full N), BK=32, 3-stage cp.async (60KB/stage),
// 8 warps = 2(m) x 4(n), warp tile 64x64, 1 CTA/SM.
// acc += Ah*Wh + Ah*Wl + Al*Wh.
// ===========================================================================
#define A_PLANE   10240           // 128 rows * 80B
#define B_PLANE   20480           // 256 rows * 80B
#define STAGE_B   61440           // 2*A_PLANE + 2*B_PLANE
#define GEMM_SMEM (3 * STAGE_B)   // 184320

template <int KDIM, int EPI, int OUTM>
__global__ __launch_bounds__(256, 1)
void gemm_mma(const __nv_bfloat16* __restrict__ A0h, const __nv_bfloat16* __restrict__ A0l,
              const __nv_bfloat16* __restrict__ A1h, const __nv_bfloat16* __restrict__ A1l,
              const __nv_bfloat16* __restrict__ Bh,  const __nv_bfloat16* __restrict__ Bl,
              float* __restrict__ outF,
              __nv_bfloat16* __restrict__ outH, __nv_bfloat16* __restrict__ outL)
{
    extern __shared__ char dsm[];
    const uint32_t sb = smem_u32(dsm);

    const int tid    = threadIdx.x;
    const int lane   = tid & 31;
    const int wid    = tid >> 5;
    const int warp_m = wid >> 2;          // 0..1 (64 rows each)
    const int warp_n = wid & 3;           // 0..3 (64 cols each)
    const int m0     = blockIdx.x * 128;
    constexpr int NIT = KDIM / 32;

    float acc[4][8][4];
#pragma unroll
    for (int mt = 0; mt < 4; ++mt)
#pragma unroll
        for (int nt = 0; nt < 8; ++nt)
#pragma unroll
            for (int q = 0; q < 4; ++q) acc[mt][nt][q] = 0.f;

    // loader: 768 rows/stage (A: 2x128, B: 2x256); thread t -> rows t, t+256, t+512
    auto load_stage = [&](int buf, int it) {
        const uint32_t st = sb + buf * STAGE_B;
        const int kc = it * 32;
        const __nv_bfloat16 *Ah, *Al;
        int kk = kc;
        if (KDIM == 512 && kc >= 256) { Ah = A1h; Al = A1l; kk = kc - 256; }
        else                          { Ah = A0h; Al = A0l; }
#pragma unroll
        for (int rr = 0; rr < 3; ++rr) {
            const int R = tid + rr * 256;
            const __nv_bfloat16* srow;
            uint32_t drow;
            if (R < 128)      { srow = Ah + (size_t)(m0 + R) * 256 + kk;        drow = st + R * 80; }
            else if (R < 256) { srow = Al + (size_t)(m0 + R - 128) * 256 + kk;  drow = st + A_PLANE + (R - 128) * 80; }
            else if (R < 512) { srow = Bh + (size_t)(R - 256) * KDIM + kc;      drow = st + 2 * A_PLANE + (R - 256) * 80; }
            else              { srow = Bl + (size_t)(R - 512) * KDIM + kc;      drow = st + 2 * A_PLANE + B_PLANE + (R - 512) * 80; }
#pragma unroll
            for (int j = 0; j < 4; ++j) cp16(drow + j * 16, srow + j * 8);
        }
    };

    load_stage(0, 0); CP_COMMIT();
    load_stage(1, 1); CP_COMMIT();

    const int g  = lane >> 3;
    const int li = lane & 7;
    const int a_r  = li + (g & 1) * 8;
    const int a_kb = (g >> 1) * 16;
    const int b_r  = li + (g >> 1) * 8;
    const int b_kb = (g & 1) * 16;

    for (int it = 0; it < NIT; ++it) {
        CP_WAIT1();
        __syncthreads();
        if (it + 2 < NIT) load_stage((it + 2) % 3, it + 2);
        CP_COMMIT();

        const uint32_t st  = sb + (it % 3) * STAGE_B;
        const uint32_t stB = st + 2 * A_PLANE;

#pragma unroll
        for (int ks = 0; ks < 2; ++ks) {
            uint32_t aH[4][4], aL[4][4];
#pragma unroll
            for (int mt = 0; mt < 4; ++mt) {
                const uint32_t ro = (uint32_t)((warp_m * 64 + mt * 16 + a_r) * 80 + ks * 32 + a_kb);
                ldsm4(aH[mt], st + ro);
                ldsm4(aL[mt], st + A_PLANE + ro);
            }
            uint32_t bH[8][2], bL[8][2];
#pragma unroll
            for (int q = 0; q < 4; ++q) {
                const uint32_t ro = (uint32_t)((warp_n * 64 + q * 16 + b_r) * 80 + ks * 32 + b_kb);
                uint32_t t[4];
                ldsm4(t, stB + ro);
                bH[q * 2][0] = t[0]; bH[q * 2][1] = t[1];
                bH[q * 2 + 1][0] = t[2]; bH[q * 2 + 1][1] = t[3];
                ldsm4(t, stB + B_PLANE + ro);
                bL[q * 2][0] = t[0]; bL[q * 2][1] = t[1];
                bL[q * 2 + 1][0] = t[2]; bL[q * 2 + 1][1] = t[3];
            }
#pragma unroll
            for (int mt = 0; mt < 4; ++mt)
#pragma unroll
                for (int nt = 0; nt < 8; ++nt)
                    mma_bf16(acc[mt][nt], aH[mt], bH[nt]);
#pragma unroll
            for (int mt = 0; mt < 4; ++mt)
#pragma unroll
                for (int nt = 0; nt < 8; ++nt)
                    mma_bf16(acc[mt][nt], aH[mt], bL[nt]);
#pragma unroll
            for (int mt = 0; mt < 4; ++mt)
#pragma unroll
                for (int nt = 0; nt < 8; ++nt)
                    mma_bf16(acc[mt][nt], aL[mt], bH[nt]);
        }
        __syncthreads();
    }

    // ------------------------- epilogue -----------------------------------
    const int orow = m0 + warp_m * 64 + (lane >> 2);
    const int ocol = warp_n * 64 + (lane & 3) * 2;
#pragma unroll
    for (int mt = 0; mt < 4; ++mt) {
#pragma unroll
        for (int nt = 0; nt < 8; ++nt) {
            const int r = orow + mt * 16;
            const int c = ocol + nt * 8;
            float v0 = epi_f<EPI>(acc[mt][nt][0]);
            float v1 = epi_f<EPI>(acc[mt][nt][1]);
            float v2 = epi_f<EPI>(acc[mt][nt][2]);
            float v3 = epi_f<EPI>(acc[mt][nt][3]);
            if (OUTM == 0) {
                float2 u0; u0.x = v0; u0.y = v1;
                float2 u1; u1.x = v2; u1.y = v3;
                *(float2*)&outF[(size_t)r * 256 + c]       = u0;
                *(float2*)&outF[(size_t)(r + 8) * 256 + c] = u1;
            } else {
                __nv_bfloat16 h0, h1, h2, h3, l0, l1, l2, l3;
                split2(v0, h0, l0); split2(v1, h1, l1);
                split2(v2, h2, l2); split2(v3, h3, l3);
                *(__nv_bfloat162*)&outH[(size_t)r * 256 + c]       = __halves2bfloat162(h0, h1);
                *(__nv_bfloat162*)&outH[(size_t)(r + 8) * 256 + c] = __halves2bfloat162(h2, h3);
                *(__nv_bfloat162*)&outL[(size_t)r * 256 + c]       = __halves2bfloat162(l0, l1);
                *(__nv_bfloat162*)&outL[(size_t)(r + 8) * 256 + c] = __halves2bfloat162(l2, l3);
            }
        }
    }
}

// ===========================================================================
// aux kernels
// ===========================================================================
__global__ void split_kernel(const float* __restrict__ in,
                             __nv_bfloat16* __restrict__ hi,
                             __nv_bfloat16* __restrict__ lo, int n4)
{
    int i = blockIdx.x * blockDim.x + threadIdx.x;
    if (i >= n4) return;
    float4 v = ((const float4*)in)[i];
    __nv_bfloat16 h0, h1, h2, h3, l0, l1, l2, l3;
    split2(v.x, h0, l0); split2(v.y, h1, l1); split2(v.z, h2, l2); split2(v.w, h3, l3);
    ((__nv_bfloat162*)hi)[i * 2 + 0] = __halves2bfloat162(h0, h1);
    ((__nv_bfloat162*)hi)[i * 2 + 1] = __halves2bfloat162(h2, h3);
    ((__nv_bfloat162*)lo)[i * 2 + 0] = __halves2bfloat162(l0, l1);
    ((__nv_bfloat162*)lo)[i * 2 + 1] = __halves2bfloat162(l2, l3);
}

// all weights in one launch: 5 x (256x256) + 1 x (512x256)
__global__ void wprep_all(const float* __restrict__ Wq, const float* __restrict__ Wk,
                          const float* __restrict__ Wv, const float* __restrict__ Wm,
                          const float* __restrict__ W2, const float* __restrict__ W1,
                          __nv_bfloat16* __restrict__ dst)
{
    int idx = blockIdx.x * blockDim.x + threadIdx.x;
    const float* W; int K; int within; __nv_bfloat16 *hi, *lo;
    if (idx < 327680) {
        int w = idx >> 16; within = idx & 65535; K = 256;
        const float* srcs[5] = {Wq, Wk, Wv, Wm, W2};
        W = srcs[w];
        int base = (w < 4) ? w * 131072 : 524288;
        hi = dst + base; lo = dst + base + 65536;
    } else if (idx < 458752) {
        within = idx - 327680; K = 512; W = W1;
        hi = dst + 655360; lo = dst + 786432;
    } else return;
    int nn = within / K, kk = within % K;
    split2(W[(size_t)kk * 256 + nn], hi[(size_t)nn * K + kk], lo[(size_t)nn * K + kk]);
}

__global__ void zero_kernel(float* p, int n)
{
    int i = blockIdx.x * blockDim.x + threadIdx.x;
    if (i < n) p[i] = 0.f;
}

__global__ __launch_bounds__(1024) void kv_reduce_kernel(
    const float* __restrict__ Kp, const float* __restrict__ Vp,
    float* __restrict__ KV, float* __restrict__ Ksum, int L)
{
    const int nh = blockIdx.x;
    const int n  = nh >> 3;
    const int h  = nh & 7;
    const int rows = L / gridDim.y;
    const int l0 = blockIdx.y * rows;
    const int tid = threadIdx.x;
    const int d = tid >> 5;
    const int e = tid & 31;

    __shared__ float sk[16][32];
    __shared__ float sv[16][32];

    const size_t base = (size_t)n * L * 256 + h * 32;
    const int ldrow = tid >> 6;
    const int ldc   = tid & 63;

    float acc = 0.f, ks = 0.f;
    for (int l = l0; l < l0 + rows; l += 16) {
        __syncthreads();
        {
            size_t off = base + (size_t)(l + ldrow) * 256;
            if (ldc < 32) sk[ldrow][ldc] = Kp[off + ldc];
            else          sv[ldrow][ldc - 32] = Vp[off + ldc - 32];
        }
        __syncthreads();
#pragma unroll
        for (int r = 0; r < 16; ++r) acc += sk[r][d] * sv[r][e];
        if (e == 0) {
#pragma unroll
            for (int r = 0; r < 16; ++r) ks += sk[r][d];
        }
    }
    atomicAdd(&KV[(size_t)nh * 1024 + d * 32 + e], acc);
    if (e == 0) atomicAdd(&Ksum[nh * 32 + d], ks);
}

__global__ __launch_bounds__(256) void msg_kernel(
    const float* __restrict__ Q, const float* __restrict__ KV,
    const float* __restrict__ Ksum,
    __nv_bfloat16* __restrict__ MH, __nv_bfloat16* __restrict__ ML, int L)
{
    const int row = blockIdx.x;
    const int n = row / L;
    const int tid = threadIdx.x;
    const int h = tid >> 5;
    const int e = tid & 31;

    __shared__ float qs[256];
    qs[tid] = Q[(size_t)row * 256 + tid];
    __syncthreads();

    float p = qs[h * 32 + e] * Ksum[(n * 8 + h) * 32 + e];
#pragma unroll
    for (int o = 16; o; o >>= 1) p += __shfl_xor_sync(0xffffffffu, p, o);
    const float z = 1.f / (p + 1e-6f);

    const float* kv = KV + (size_t)(n * 8 + h) * 1024;
    float acc = 0.f;
#pragma unroll
    for (int dd = 0; dd < 32; ++dd) acc += qs[h * 32 + dd] * kv[dd * 32 + e];

    split2(acc * z, MH[(size_t)row * 256 + tid], ML[(size_t)row * 256 + tid]);
}

template <int OUT>
__global__ __launch_bounds__(256) void ln_kernel(
    const float* __restrict__ in, const float* __restrict__ res,
    const float* __restrict__ g, const float* __restrict__ b,
    float* __restrict__ outf,
    __nv_bfloat16* __restrict__ oh, __nv_bfloat16* __restrict__ ol, int rows)
{
    const int gw = (int)((blockIdx.x * blockDim.x + threadIdx.x) >> 5);
    if (gw >= rows) return;
    const int lane = threadIdx.x & 31;

    const float4* rp = (const float4*)(in + (size_t)gw * 256);
    float v[8];
    *(float4*)&v[0] = rp[lane];
    *(float4*)&v[4] = rp[lane + 32];

    float s = 0.f;
#pragma unroll
    for (int i = 0; i < 8; ++i) s += v[i];
#pragma unroll
    for (int o = 16; o; o >>= 1) s += __shfl_xor_sync(0xffffffffu, s, o);
    const float mu = s * (1.f / 256.f);

    float vs = 0.f;
#pragma unroll
    for (int i = 0; i < 8; ++i) { v[i] -= mu; vs += v[i] * v[i]; }
#pragma unroll
    for (int o = 16; o; o >>= 1) vs += __shfl_xor_sync(0xffffffffu, vs, o);
    const float rstd = rsqrtf(vs * (1.f / 256.f) + 1e-5f);

    float G[8], Bv[8];
    *(float4*)&G[0]  = ((const float4*)g)[lane];
    *(float4*)&G[4]  = ((const float4*)g)[lane + 32];
    *(float4*)&Bv[0] = ((const float4*)b)[lane];
    *(float4*)&Bv[4] = ((const float4*)b)[lane + 32];

    float o8[8];
#pragma unroll
    for (int i = 0; i < 8; ++i) o8[i] = v[i] * rstd * G[i] + Bv[i];

    if (OUT == 0) {
        if (res) {
            const float4* xp = (const float4*)(res + (size_t)gw * 256);
            float r8[8];
            *(float4*)&r8[0] = xp[lane];
            *(float4*)&r8[4] = xp[lane + 32];
#pragma unroll
            for (int i = 0; i < 8; ++i) o8[i] += r8[i];
        }
        float4* op = (float4*)(outf + (size_t)gw * 256);
        op[lane]      = *(float4*)&o8[0];
        op[lane + 32] = *(float4*)&o8[4];
    } else {
        __nv_bfloat16 h[8], l[8];
#pragma unroll
        for (int i = 0; i < 8; ++i) split2(o8[i], h[i], l[i]);
        __nv_bfloat162* ph0 = (__nv_bfloat162*)(oh + (size_t)gw * 256 + lane * 4);
        __nv_bfloat162* ph1 = (__nv_bfloat162*)(oh + (size_t)gw * 256 + 128 + lane * 4);
        __nv_bfloat162* pl0 = (__nv_bfloat162*)(ol + (size_t)gw * 256 + lane * 4);
        __nv_bfloat162* pl1 = (__nv_bfloat162*)(ol + (size_t)gw * 256 + 128 + lane * 4);
        ph0[0] = __halves2bfloat162(h[0], h[1]); ph0[1] = __halves2bfloat162(h[2], h[3]);
        ph1[0] = __halves2bfloat162(h[4], h[5]); ph1[1] = __halves2bfloat162(h[6], h[7]);
        pl0[0] = __halves2bfloat162(l[0], l[1]); pl0[1] = __halves2bfloat162(l[2], l[3]);
        pl1[0] = __halves2bfloat162(l[4], l[5]); pl1[1] = __halves2bfloat162(l[6], l[7]);
    }
}

// ===========================================================================
// launch
// ===========================================================================
extern "C" void kernel_launch(void* const* d_in, const int* in_sizes, int n_in,
                              void* d_out, int out_size)
{
    const float* x  = (const float*)d_in[0];
    const float* Wq = (const float*)d_in[1];
    const float* Wk = (const float*)d_in[2];
    const float* Wv = (const float*)d_in[3];
    const float* Wm = (const float*)d_in[4];
    const float* W1 = (const float*)d_in[5];
    const float* W2 = (const float*)d_in[6];
    const float* g1 = (const float*)d_in[7];
    const float* b1 = (const float*)d_in[8];
    const float* g2 = (const float*)d_in[9];
    const float* b2 = (const float*)d_in[10];

    const int M = in_sizes[0] / C_DIM;   // 65536
    const int L = M / NB;                // 16384

    float *Qf, *Kf, *Vf, *sm;
    __nv_bfloat16 *xhi, *xlo, *mhi, *mlo, *lhi, *llo, *hhi, *hlo, *gw;
    cudaGetSymbolAddress((void**)&Qf, g_Q);
    cudaGetSymbolAddress((void**)&Kf, g_K);
    cudaGetSymbolAddress((void**)&Vf, g_V);
    cudaGetSymbolAddress((void**)&xhi, g_xhi);
    cudaGetSymbolAddress((void**)&xlo, g_xlo);
    cudaGetSymbolAddress((void**)&mhi, g_mhi);
    cudaGetSymbolAddress((void**)&mlo, g_mlo);
    cudaGetSymbolAddress((void**)&lhi, g_lhi);
    cudaGetSymbolAddress((void**)&llo, g_llo);
    cudaGetSymbolAddress((void**)&hhi, g_hhi);
    cudaGetSymbolAddress((void**)&hlo, g_hlo);
    cudaGetSymbolAddress((void**)&gw, g_w);
    cudaGetSymbolAddress((void**)&sm, g_small);
    float* KV   = sm;
    float* Ksum = sm + 32 * 1024;

    __nv_bfloat16 *wqh = gw,           *wql = gw + 65536;
    __nv_bfloat16 *wkh = gw + 131072,  *wkl = gw + 196608;
    __nv_bfloat16 *wvh = gw + 262144,  *wvl = gw + 327680;
    __nv_bfloat16 *wmh = gw + 393216,  *wml = gw + 458752;
    __nv_bfloat16 *w2h = gw + 524288,  *w2l = gw + 589824;
    __nv_bfloat16 *w1h = gw + 655360,  *w1l = gw + 786432;

    cudaFuncSetAttribute(gemm_mma<256, 1, 0>, cudaFuncAttributeMaxDynamicSharedMemorySize, GEMM_SMEM);
    cudaFuncSetAttribute(gemm_mma<256, 0, 0>, cudaFuncAttributeMaxDynamicSharedMemorySize, GEMM_SMEM);
    cudaFuncSetAttribute(gemm_mma<512, 2, 1>, cudaFuncAttributeMaxDynamicSharedMemorySize, GEMM_SMEM);

    wprep_all<<<(458752 + 255) / 256, 256>>>(Wq, Wk, Wv, Wm, W2, W1, gw);
    split_kernel<<<(M * 64 + 255) / 256, 256>>>(x, xhi, xlo, M * 64);

    const int GB = M / 128;   // 512 CTAs, full N per CTA

    gemm_mma<256, 1, 0><<<GB, 256, GEMM_SMEM>>>(xhi, xlo, nullptr, nullptr, wqh, wql, Qf, nullptr, nullptr);
    gemm_mma<256, 1, 0><<<GB, 256, GEMM_SMEM>>>(xhi, xlo, nullptr, nullptr, wkh, wkl, Kf, nullptr, nullptr);
    gemm_mma<256, 0, 0><<<GB, 256, GEMM_SMEM>>>(xhi, xlo, nullptr, nullptr, wvh, wvl, Vf, nullptr, nullptr);

    zero_kernel<<<(33792 + 255) / 256, 256>>>(sm, 33792);
    kv_reduce_kernel<<<dim3(32, 64), 1024>>>(Kf, Vf, KV, Ksum, L);

    msg_kernel<<<M, 256>>>(Qf, KV, Ksum, mhi, mlo, L);

    gemm_mma<256, 0, 0><<<GB, 256, GEMM_SMEM>>>(mhi, mlo, nullptr, nullptr, wmh, wml, Kf, nullptr, nullptr);
    ln_kernel<1><<<M / 8, 256>>>(Kf, nullptr, g1, b1, nullptr, lhi, llo, M);

    gemm_mma<512, 2, 1><<<GB, 256, GEMM_SMEM>>>(xhi, xlo, lhi, llo, w1h, w1l, nullptr, hhi, hlo);

    gemm_mma<256, 0, 0><<<GB, 256, GEMM_SMEM>>>(hhi, hlo, nullptr, nullptr, w2h, w2l, Vf, nullptr, nullptr);
    ln_kernel<0><<<M / 8, 256>>>(Vf, x, g2, b2, (float*)d_out, nullptr, nullptr, M);
}

// round 9
// speedup vs baseline: 1.5230x; 1.4873x over previous
#include <cuda_runtime.h>
#include <cuda_fp16.h>
#include <cstdint>
#include <cstddef>

// ===========================================================================
// StructureAttention, mma.sync fp16 single-plane (m16n8k16.f32.f16.f16.f32).
// R9: legacy HMMA path is rate-limited (~0.25 HMMA/cyc/SM); win by issuing
// 3x fewer MMAs: fp16 (11-bit mantissa) single plane instead of bf16 hi/lo x3.
// Error ~1.5e-4 << 1e-3 gate.
// ===========================================================================

#define C_DIM 256
#define NB    4
#define MTOT  16777216

__device__ float g_Q[MTOT];
__device__ float g_K[MTOT];
__device__ float g_V[MTOT];
__device__ __half g_xh[MTOT];
__device__ __half g_mh[MTOT];
__device__ __half g_lh[MTOT];
__device__ __half g_hh[MTOT];
__device__ __half g_w[458752];
__device__ float g_small[32 * 1024 + 32 * 32];

// ---------------- helpers --------------------------------------------------
__device__ __forceinline__ uint32_t smem_u32(const void* p) {
    uint32_t a;
    asm("{ .reg .u64 t; cvta.to.shared.u64 t, %1; cvt.u32.u64 %0, t; }" : "=r"(a) : "l"(p));
    return a;
}
__device__ __forceinline__ void cp16(uint32_t dst, const void* src) {
    asm volatile("cp.async.cg.shared.global [%0], [%1], 16;"
                 :: "r"(dst), "l"(__cvta_generic_to_global(src)) : "memory");
}
#define CP_COMMIT() asm volatile("cp.async.commit_group;" ::: "memory")
#define CP_WAIT1()  asm volatile("cp.async.wait_group 1;"  ::: "memory")

__device__ __forceinline__ void ldsm4(uint32_t* r, uint32_t addr) {
    asm volatile("ldmatrix.sync.aligned.m8n8.x4.shared.b16 {%0,%1,%2,%3}, [%4];"
                 : "=r"(r[0]), "=r"(r[1]), "=r"(r[2]), "=r"(r[3]) : "r"(addr));
}
__device__ __forceinline__ void mma_fp16(float* c, const uint32_t* a, const uint32_t* b) {
    asm("mma.sync.aligned.m16n8k16.row.col.f32.f16.f16.f32 "
        "{%0,%1,%2,%3}, {%4,%5,%6,%7}, {%8,%9}, {%0,%1,%2,%3};"
        : "+f"(c[0]), "+f"(c[1]), "+f"(c[2]), "+f"(c[3])
        : "r"(a[0]), "r"(a[1]), "r"(a[2]), "r"(a[3]), "r"(b[0]), "r"(b[1]));
}
template <int EPI>
__device__ __forceinline__ float epi_f(float t) {
    if (EPI == 1) return t > 0.f ? t + 1.f : __expf(t);   // phi = elu+1
    if (EPI == 2) return fmaxf(t, 0.f);                   // relu
    return t;
}

// ===========================================================================
// HMMA GEMM: out[M,256] = A[M,KDIM] * W[KDIM,256]; W transposed
// (Wt[256,KDIM], k-contiguous) fp16; A fp16 (row len 256; KDIM=512 ->
// second A pointer = cols 256..511).
// CTA 128x256 (full N), BK=32, 3-stage cp.async (30KB/stage),
// 8 warps = 2(m) x 4(n), warp tile 64x64, fp32 accum.
// ===========================================================================
#define A_PLANE   10240           // 128 rows * 80B
#define B_PLANE   20480           // 256 rows * 80B
#define STAGE_B   30720
#define GEMM_SMEM (3 * STAGE_B)   // 92160

template <int KDIM, int EPI, int OUTM>
__global__ __launch_bounds__(256, 1)
void gemm_mma(const __half* __restrict__ A0, const __half* __restrict__ A1,
              const __half* __restrict__ B,
              float* __restrict__ outF, __half* __restrict__ outH)
{
    extern __shared__ char dsm[];
    const uint32_t sb = smem_u32(dsm);

    const int tid    = threadIdx.x;
    const int lane   = tid & 31;
    const int wid    = tid >> 5;
    const int warp_m = wid >> 2;          // 0..1 (64 rows)
    const int warp_n = wid & 3;           // 0..3 (64 cols)
    const int m0     = blockIdx.x * 128;
    constexpr int NIT = KDIM / 32;

    float acc[4][8][4];
#pragma unroll
    for (int mt = 0; mt < 4; ++mt)
#pragma unroll
        for (int nt = 0; nt < 8; ++nt)
#pragma unroll
            for (int q = 0; q < 4; ++q) acc[mt][nt][q] = 0.f;

    // loader: 384 rows/stage (A:128, B:256); 2 passes of 256 threads.
    auto load_stage = [&](int buf, int it) {
        const uint32_t st = sb + buf * STAGE_B;
        const int kc = it * 32;
        const __half* Ap; int kk = kc;
        if (KDIM == 512 && kc >= 256) { Ap = A1; kk = kc - 256; }
        else                          { Ap = A0; }
#pragma unroll
        for (int rr = 0; rr < 2; ++rr) {
            const int R = tid + rr * 256;
            if (R < 128) {
                const __half* srow = Ap + (size_t)(m0 + R) * 256 + kk;
                const uint32_t drow = st + R * 80;
#pragma unroll
                for (int j = 0; j < 4; ++j) cp16(drow + j * 16, srow + j * 8);
            } else if (R < 384) {
                const __half* srow = B + (size_t)(R - 128) * KDIM + kc;
                const uint32_t drow = st + A_PLANE + (R - 128) * 80;
#pragma unroll
                for (int j = 0; j < 4; ++j) cp16(drow + j * 16, srow + j * 8);
            }
        }
    };

    load_stage(0, 0); CP_COMMIT();
    load_stage(1, 1); CP_COMMIT();

    const int g  = lane >> 3;
    const int li = lane & 7;
    const int a_r  = li + (g & 1) * 8;
    const int a_kb = (g >> 1) * 16;
    const int b_r  = li + (g >> 1) * 8;
    const int b_kb = (g & 1) * 16;

    for (int it = 0; it < NIT; ++it) {
        CP_WAIT1();
        __syncthreads();
        if (it + 2 < NIT) load_stage((it + 2) % 3, it + 2);
        CP_COMMIT();

        const uint32_t st  = sb + (it % 3) * STAGE_B;
        const uint32_t stB = st + A_PLANE;

#pragma unroll
        for (int ks = 0; ks < 2; ++ks) {
            uint32_t aF[4][4];
#pragma unroll
            for (int mt = 0; mt < 4; ++mt) {
                const uint32_t ro = (uint32_t)((warp_m * 64 + mt * 16 + a_r) * 80 + ks * 32 + a_kb);
                ldsm4(aF[mt], st + ro);
            }
            uint32_t bF[8][2];
#pragma unroll
            for (int q = 0; q < 4; ++q) {
                const uint32_t ro = (uint32_t)((warp_n * 64 + q * 16 + b_r) * 80 + ks * 32 + b_kb);
                uint32_t t[4];
                ldsm4(t, stB + ro);
                bF[q * 2][0] = t[0]; bF[q * 2][1] = t[1];
                bF[q * 2 + 1][0] = t[2]; bF[q * 2 + 1][1] = t[3];
            }
#pragma unroll
            for (int mt = 0; mt < 4; ++mt)
#pragma unroll
                for (int nt = 0; nt < 8; ++nt)
                    mma_fp16(acc[mt][nt], aF[mt], bF[nt]);
        }
        __syncthreads();
    }

    // ------------------------- epilogue -----------------------------------
    const int orow = m0 + warp_m * 64 + (lane >> 2);
    const int ocol = warp_n * 64 + (lane & 3) * 2;
#pragma unroll
    for (int mt = 0; mt < 4; ++mt) {
#pragma unroll
        for (int nt = 0; nt < 8; ++nt) {
            const int r = orow + mt * 16;
            const int c = ocol + nt * 8;
            float v0 = epi_f<EPI>(acc[mt][nt][0]);
            float v1 = epi_f<EPI>(acc[mt][nt][1]);
            float v2 = epi_f<EPI>(acc[mt][nt][2]);
            float v3 = epi_f<EPI>(acc[mt][nt][3]);
            if (OUTM == 0) {
                float2 u0; u0.x = v0; u0.y = v1;
                float2 u1; u1.x = v2; u1.y = v3;
                *(float2*)&outF[(size_t)r * 256 + c]       = u0;
                *(float2*)&outF[(size_t)(r + 8) * 256 + c] = u1;
            } else {
                *(__half2*)&outH[(size_t)r * 256 + c]       = __floats2half2_rn(v0, v1);
                *(__half2*)&outH[(size_t)(r + 8) * 256 + c] = __floats2half2_rn(v2, v3);
            }
        }
    }
}

// ===========================================================================
// aux kernels
// ===========================================================================
__global__ void split_kernel(const float* __restrict__ in,
                             __half* __restrict__ out, int n4)
{
    int i = blockIdx.x * blockDim.x + threadIdx.x;
    if (i >= n4) return;
    float4 v = ((const float4*)in)[i];
    ((__half2*)out)[i * 2 + 0] = __floats2half2_rn(v.x, v.y);
    ((__half2*)out)[i * 2 + 1] = __floats2half2_rn(v.z, v.w);
}

// all weights in one launch, transposed to [N, K] fp16.
// layout: wq@0 wk@65536 wv@131072 wm@196608 w2@262144 (K=256); w1@327680 (K=512)
__global__ void wprep_all(const float* __restrict__ Wq, const float* __restrict__ Wk,
                          const float* __restrict__ Wv, const float* __restrict__ Wm,
                          const float* __restrict__ W2, const float* __restrict__ W1,
                          __half* __restrict__ dst)
{
    int idx = blockIdx.x * blockDim.x + threadIdx.x;
    const float* W; int K; int within; __half* o;
    if (idx < 327680) {
        int w = idx >> 16; within = idx & 65535; K = 256;
        const float* srcs[5] = {Wq, Wk, Wv, Wm, W2};
        W = srcs[w];
        o = dst + w * 65536;
    } else if (idx < 458752) {
        within = idx - 327680; K = 512; W = W1;
        o = dst + 327680;
    } else return;
    int nn = within / K, kk = within % K;
    o[(size_t)nn * K + kk] = __float2half_rn(W[(size_t)kk * 256 + nn]);
}

__global__ void zero_kernel(float* p, int n)
{
    int i = blockIdx.x * blockDim.x + threadIdx.x;
    if (i < n) p[i] = 0.f;
}

// 64-row chunks (8 barriers/block instead of 32)
__global__ __launch_bounds__(1024) void kv_reduce_kernel(
    const float* __restrict__ Kp, const float* __restrict__ Vp,
    float* __restrict__ KV, float* __restrict__ Ksum, int L)
{
    const int nh = blockIdx.x;
    const int n  = nh >> 3;
    const int h  = nh & 7;
    const int rows = L / gridDim.y;        // 256
    const int l0 = blockIdx.y * rows;
    const int tid = threadIdx.x;
    const int d = tid >> 5;
    const int e = tid & 31;

    __shared__ float sk[64][32];
    __shared__ float sv[64][32];

    const size_t base = (size_t)n * L * 256 + h * 32;

    float acc = 0.f, ks = 0.f;
    for (int l = l0; l < l0 + rows; l += 64) {
        __syncthreads();
#pragma unroll
        for (int c = 0; c < 4; ++c) {
            const int idx = tid + c * 1024;       // 0..4095
            const int row = idx >> 6;
            const int col = idx & 63;
            size_t off = base + (size_t)(l + row) * 256;
            if (col < 32) sk[row][col] = Kp[off + col];
            else          sv[row][col - 32] = Vp[off + col - 32];
        }
        __syncthreads();
#pragma unroll
        for (int r = 0; r < 64; ++r) acc += sk[r][d] * sv[r][e];
        if (e == 0) {
#pragma unroll
            for (int r = 0; r < 64; ++r) ks += sk[r][d];
        }
    }
    atomicAdd(&KV[(size_t)nh * 1024 + d * 32 + e], acc);
    if (e == 0) atomicAdd(&Ksum[nh * 32 + d], ks);
}

__global__ __launch_bounds__(256) void msg_kernel(
    const float* __restrict__ Q, const float* __restrict__ KV,
    const float* __restrict__ Ksum,
    __half* __restrict__ MH, int L)
{
    const int row = blockIdx.x;
    const int n = row / L;
    const int tid = threadIdx.x;
    const int h = tid >> 5;
    const int e = tid & 31;

    __shared__ float qs[256];
    qs[tid] = Q[(size_t)row * 256 + tid];
    __syncthreads();

    float p = qs[h * 32 + e] * Ksum[(n * 8 + h) * 32 + e];
#pragma unroll
    for (int o = 16; o; o >>= 1) p += __shfl_xor_sync(0xffffffffu, p, o);
    const float z = 1.f / (p + 1e-6f);

    const float* kv = KV + (size_t)(n * 8 + h) * 1024;
    float acc = 0.f;
#pragma unroll
    for (int dd = 0; dd < 32; ++dd) acc += qs[h * 32 + dd] * kv[dd * 32 + e];

    MH[(size_t)row * 256 + tid] = __float2half_rn(acc * z);
}

// OUT=0: fp32 (+optional residual).  OUT=1: fp16.
template <int OUT>
__global__ __launch_bounds__(256) void ln_kernel(
    const float* __restrict__ in, const float* __restrict__ res,
    const float* __restrict__ g, const float* __restrict__ b,
    float* __restrict__ outf, __half* __restrict__ oh, int rows)
{
    const int gw = (int)((blockIdx.x * blockDim.x + threadIdx.x) >> 5);
    if (gw >= rows) return;
    const int lane = threadIdx.x & 31;

    const float4* rp = (const float4*)(in + (size_t)gw * 256);
    float v[8];
    *(float4*)&v[0] = rp[lane];
    *(float4*)&v[4] = rp[lane + 32];

    float s = 0.f;
#pragma unroll
    for (int i = 0; i < 8; ++i) s += v[i];
#pragma unroll
    for (int o = 16; o; o >>= 1) s += __shfl_xor_sync(0xffffffffu, s, o);
    const float mu = s * (1.f / 256.f);

    float vs = 0.f;
#pragma unroll
    for (int i = 0; i < 8; ++i) { v[i] -= mu; vs += v[i] * v[i]; }
#pragma unroll
    for (int o = 16; o; o >>= 1) vs += __shfl_xor_sync(0xffffffffu, vs, o);
    const float rstd = rsqrtf(vs * (1.f / 256.f) + 1e-5f);

    float G[8], Bv[8];
    *(float4*)&G[0]  = ((const float4*)g)[lane];
    *(float4*)&G[4]  = ((const float4*)g)[lane + 32];
    *(float4*)&Bv[0] = ((const float4*)b)[lane];
    *(float4*)&Bv[4] = ((const float4*)b)[lane + 32];

    float o8[8];
#pragma unroll
    for (int i = 0; i < 8; ++i) o8[i] = v[i] * rstd * G[i] + Bv[i];

    if (OUT == 0) {
        if (res) {
            const float4* xp = (const float4*)(res + (size_t)gw * 256);
            float r8[8];
            *(float4*)&r8[0] = xp[lane];
            *(float4*)&r8[4] = xp[lane + 32];
#pragma unroll
            for (int i = 0; i < 8; ++i) o8[i] += r8[i];
        }
        float4* op = (float4*)(outf + (size_t)gw * 256);
        op[lane]      = *(float4*)&o8[0];
        op[lane + 32] = *(float4*)&o8[4];
    } else {
        __half2* p0 = (__half2*)(oh + (size_t)gw * 256 + lane * 4);
        __half2* p1 = (__half2*)(oh + (size_t)gw * 256 + 128 + lane * 4);
        p0[0] = __floats2half2_rn(o8[0], o8[1]);
        p0[1] = __floats2half2_rn(o8[2], o8[3]);
        p1[0] = __floats2half2_rn(o8[4], o8[5]);
        p1[1] = __floats2half2_rn(o8[6], o8[7]);
    }
}

// ===========================================================================
// launch
// ===========================================================================
extern "C" void kernel_launch(void* const* d_in, const int* in_sizes, int n_in,
                              void* d_out, int out_size)
{
    const float* x  = (const float*)d_in[0];
    const float* Wq = (const float*)d_in[1];
    const float* Wk = (const float*)d_in[2];
    const float* Wv = (const float*)d_in[3];
    const float* Wm = (const float*)d_in[4];
    const float* W1 = (const float*)d_in[5];
    const float* W2 = (const float*)d_in[6];
    const float* g1 = (const float*)d_in[7];
    const float* b1 = (const float*)d_in[8];
    const float* g2 = (const float*)d_in[9];
    const float* b2 = (const float*)d_in[10];

    const int M = in_sizes[0] / C_DIM;   // 65536
    const int L = M / NB;                // 16384

    float *Qf, *Kf, *Vf, *sm;
    __half *xh, *mh, *lh, *hh, *gw;
    cudaGetSymbolAddress((void**)&Qf, g_Q);
    cudaGetSymbolAddress((void**)&Kf, g_K);
    cudaGetSymbolAddress((void**)&Vf, g_V);
    cudaGetSymbolAddress((void**)&xh, g_xh);
    cudaGetSymbolAddress((void**)&mh, g_mh);
    cudaGetSymbolAddress((void**)&lh, g_lh);
    cudaGetSymbolAddress((void**)&hh, g_hh);
    cudaGetSymbolAddress((void**)&gw, g_w);
    cudaGetSymbolAddress((void**)&sm, g_small);
    float* KV   = sm;
    float* Ksum = sm + 32 * 1024;

    __half *wq = gw;
    __half *wk = gw + 65536;
    __half *wv = gw + 131072;
    __half *wm = gw + 196608;
    __half *w2 = gw + 262144;
    __half *w1 = gw + 327680;

    cudaFuncSetAttribute(gemm_mma<256, 1, 0>, cudaFuncAttributeMaxDynamicSharedMemorySize, GEMM_SMEM);
    cudaFuncSetAttribute(gemm_mma<256, 0, 0>, cudaFuncAttributeMaxDynamicSharedMemorySize, GEMM_SMEM);
    cudaFuncSetAttribute(gemm_mma<512, 2, 1>, cudaFuncAttributeMaxDynamicSharedMemorySize, GEMM_SMEM);

    wprep_all<<<(458752 + 255) / 256, 256>>>(Wq, Wk, Wv, Wm, W2, W1, gw);
    split_kernel<<<(M * 64 + 255) / 256, 256>>>(x, xh, M * 64);

    const int GB = M / 128;   // 512 CTAs, full N per CTA

    gemm_mma<256, 1, 0><<<GB, 256, GEMM_SMEM>>>(xh, nullptr, wq, Qf, nullptr);
    gemm_mma<256, 1, 0><<<GB, 256, GEMM_SMEM>>>(xh, nullptr, wk, Kf, nullptr);
    gemm_mma<256, 0, 0><<<GB, 256, GEMM_SMEM>>>(xh, nullptr, wv, Vf, nullptr);

    zero_kernel<<<(33792 + 255) / 256, 256>>>(sm, 33792);
    kv_reduce_kernel<<<dim3(32, 64), 1024>>>(Kf, Vf, KV, Ksum, L);

    msg_kernel<<<M, 256>>>(Qf, KV, Ksum, mh, L);

    gemm_mma<256, 0, 0><<<GB, 256, GEMM_SMEM>>>(mh, nullptr, wm, Kf, nullptr);
    ln_kernel<1><<<M / 8, 256>>>(Kf, nullptr, g1, b1, nullptr, lh, M);

    gemm_mma<512, 2, 1><<<GB, 256, GEMM_SMEM>>>(xh, lh, w1, nullptr, hh);

    gemm_mma<256, 0, 0><<<GB, 256, GEMM_SMEM>>>(hh, nullptr, w2, Vf, nullptr);
    ln_kernel<0><<<M / 8, 256>>>(Vf, x, g2, b2, (float*)d_out, nullptr, M);
}

// round 10
// speedup vs baseline: 1.5652x; 1.0277x over previous
#include <cuda_runtime.h>
#include <cuda_fp16.h>
#include <cstdint>
#include <cstddef>

// ===========================================================================
// StructureAttention, mma.sync fp16 single-plane, fp32 accum.
// R10: LayerNorms fused into GEMM epilogues (CTA covers full N=256, so the
// row reduction is intra-CTA). Removes 2 LN launches + 2 fp32 round trips.
// ===========================================================================

#define C_DIM 256
#define NB    4
#define MTOT  16777216

__device__ float g_Q[MTOT];
__device__ float g_K[MTOT];
__device__ float g_V[MTOT];
__device__ __half g_xh[MTOT];
__device__ __half g_mh[MTOT];
__device__ __half g_lh[MTOT];
__device__ __half g_hh[MTOT];
__device__ __half g_w[458752];
__device__ float g_small[32 * 1024 + 32 * 32];

// ---------------- helpers --------------------------------------------------
__device__ __forceinline__ uint32_t smem_u32(const void* p) {
    uint32_t a;
    asm("{ .reg .u64 t; cvta.to.shared.u64 t, %1; cvt.u32.u64 %0, t; }" : "=r"(a) : "l"(p));
    return a;
}
__device__ __forceinline__ void cp16(uint32_t dst, const void* src) {
    asm volatile("cp.async.cg.shared.global [%0], [%1], 16;"
                 :: "r"(dst), "l"(__cvta_generic_to_global(src)) : "memory");
}
#define CP_COMMIT() asm volatile("cp.async.commit_group;" ::: "memory")
#define CP_WAIT1()  asm volatile("cp.async.wait_group 1;"  ::: "memory")

__device__ __forceinline__ void ldsm4(uint32_t* r, uint32_t addr) {
    asm volatile("ldmatrix.sync.aligned.m8n8.x4.shared.b16 {%0,%1,%2,%3}, [%4];"
                 : "=r"(r[0]), "=r"(r[1]), "=r"(r[2]), "=r"(r[3]) : "r"(addr));
}
__device__ __forceinline__ void mma_fp16(float* c, const uint32_t* a, const uint32_t* b) {
    asm("mma.sync.aligned.m16n8k16.row.col.f32.f16.f16.f32 "
        "{%0,%1,%2,%3}, {%4,%5,%6,%7}, {%8,%9}, {%0,%1,%2,%3};"
        : "+f"(c[0]), "+f"(c[1]), "+f"(c[2]), "+f"(c[3])
        : "r"(a[0]), "r"(a[1]), "r"(a[2]), "r"(a[3]), "r"(b[0]), "r"(b[1]));
}
template <int EPI>
__device__ __forceinline__ float epi_f(float t) {
    if (EPI == 1) return t > 0.f ? t + 1.f : __expf(t);   // phi = elu+1
    if (EPI == 2) return fmaxf(t, 0.f);                   // relu
    return t;
}

// ===========================================================================
// HMMA GEMM: out[M,256] = A[M,KDIM] * W[KDIM,256]; W transposed fp16
// (Wt[256,KDIM]); A fp16 (row len 256; KDIM=512 -> A1 = cols 256..511).
// CTA 128x256 (full N), BK=32, 3-stage cp.async, 8 warps = 2(m)x4(n),
// warp tile 64x64, fp32 accum.
// OUTM: 0 = fp32 out, 1 = fp16 out, 2 = LN + fp16 out, 3 = LN + res + fp32.
// ===========================================================================
#define A_PLANE   10240           // 128 rows * 80B
#define STAGE_B   30720
#define GEMM_SMEM (3 * STAGE_B)   // 92160

template <int KDIM, int EPI, int OUTM>
__global__ __launch_bounds__(256, 1)
void gemm_mma(const __half* __restrict__ A0, const __half* __restrict__ A1,
              const __half* __restrict__ B,
              float* __restrict__ outF, __half* __restrict__ outH,
              const float* __restrict__ lng, const float* __restrict__ lnb,
              const float* __restrict__ res)
{
    extern __shared__ char dsm[];
    const uint32_t sb = smem_u32(dsm);

    const int tid    = threadIdx.x;
    const int lane   = tid & 31;
    const int wid    = tid >> 5;
    const int warp_m = wid >> 2;          // 0..1 (64 rows)
    const int warp_n = wid & 3;           // 0..3 (64 cols)
    const int m0     = blockIdx.x * 128;
    constexpr int NIT = KDIM / 32;

    float acc[4][8][4];
#pragma unroll
    for (int mt = 0; mt < 4; ++mt)
#pragma unroll
        for (int nt = 0; nt < 8; ++nt)
#pragma unroll
            for (int q = 0; q < 4; ++q) acc[mt][nt][q] = 0.f;

    auto load_stage = [&](int buf, int it) {
        const uint32_t st = sb + buf * STAGE_B;
        const int kc = it * 32;
        const __half* Ap; int kk = kc;
        if (KDIM == 512 && kc >= 256) { Ap = A1; kk = kc - 256; }
        else                          { Ap = A0; }
#pragma unroll
        for (int rr = 0; rr < 2; ++rr) {
            const int R = tid + rr * 256;
            if (R < 128) {
                const __half* srow = Ap + (size_t)(m0 + R) * 256 + kk;
                const uint32_t drow = st + R * 80;
#pragma unroll
                for (int j = 0; j < 4; ++j) cp16(drow + j * 16, srow + j * 8);
            } else if (R < 384) {
                const __half* srow = B + (size_t)(R - 128) * KDIM + kc;
                const uint32_t drow = st + A_PLANE + (R - 128) * 80;
#pragma unroll
                for (int j = 0; j < 4; ++j) cp16(drow + j * 16, srow + j * 8);
            }
        }
    };

    load_stage(0, 0); CP_COMMIT();
    load_stage(1, 1); CP_COMMIT();

    const int g  = lane >> 3;
    const int li = lane & 7;
    const int a_r  = li + (g & 1) * 8;
    const int a_kb = (g >> 1) * 16;
    const int b_r  = li + (g >> 1) * 8;
    const int b_kb = (g & 1) * 16;

    for (int it = 0; it < NIT; ++it) {
        CP_WAIT1();
        __syncthreads();
        if (it + 2 < NIT) load_stage((it + 2) % 3, it + 2);
        CP_COMMIT();

        const uint32_t st  = sb + (it % 3) * STAGE_B;
        const uint32_t stB = st + A_PLANE;

#pragma unroll
        for (int ks = 0; ks < 2; ++ks) {
            uint32_t aF[4][4];
#pragma unroll
            for (int mt = 0; mt < 4; ++mt) {
                const uint32_t ro = (uint32_t)((warp_m * 64 + mt * 16 + a_r) * 80 + ks * 32 + a_kb);
                ldsm4(aF[mt], st + ro);
            }
            uint32_t bF[8][2];
#pragma unroll
            for (int q = 0; q < 4; ++q) {
                const uint32_t ro = (uint32_t)((warp_n * 64 + q * 16 + b_r) * 80 + ks * 32 + b_kb);
                uint32_t t[4];
                ldsm4(t, stB + ro);
                bF[q * 2][0] = t[0]; bF[q * 2][1] = t[1];
                bF[q * 2 + 1][0] = t[2]; bF[q * 2 + 1][1] = t[3];
            }
#pragma unroll
            for (int mt = 0; mt < 4; ++mt)
#pragma unroll
                for (int nt = 0; nt < 8; ++nt)
                    mma_fp16(acc[mt][nt], aF[mt], bF[nt]);
        }
        __syncthreads();
    }

    // ------------------------- epilogue -----------------------------------
    const int orow = m0 + warp_m * 64 + (lane >> 2);
    const int ocol = warp_n * 64 + (lane & 3) * 2;

    if (OUTM <= 1) {
#pragma unroll
        for (int mt = 0; mt < 4; ++mt) {
#pragma unroll
            for (int nt = 0; nt < 8; ++nt) {
                const int r = orow + mt * 16;
                const int c = ocol + nt * 8;
                float v0 = epi_f<EPI>(acc[mt][nt][0]);
                float v1 = epi_f<EPI>(acc[mt][nt][1]);
                float v2 = epi_f<EPI>(acc[mt][nt][2]);
                float v3 = epi_f<EPI>(acc[mt][nt][3]);
                if (OUTM == 0) {
                    float2 u0; u0.x = v0; u0.y = v1;
                    float2 u1; u1.x = v2; u1.y = v3;
                    *(float2*)&outF[(size_t)r * 256 + c]       = u0;
                    *(float2*)&outF[(size_t)(r + 8) * 256 + c] = u1;
                } else {
                    *(__half2*)&outH[(size_t)r * 256 + c]       = __floats2half2_rn(v0, v1);
                    *(__half2*)&outH[(size_t)(r + 8) * 256 + c] = __floats2half2_rn(v2, v3);
                }
            }
        }
    } else {
        // fused LayerNorm over the 256-wide row (EPI must be 0 here).
        float* sbuf = (float*)dsm;             // [4 warp_n][128 rows][2]
        float rs[8], rq[8];                    // per (mt, half): sum, sumsq
#pragma unroll
        for (int mt = 0; mt < 4; ++mt) {
#pragma unroll
            for (int h2 = 0; h2 < 2; ++h2) {
                float s = 0.f, q = 0.f;
#pragma unroll
                for (int nt = 0; nt < 8; ++nt) {
                    float u0 = acc[mt][nt][h2 * 2], u1 = acc[mt][nt][h2 * 2 + 1];
                    s += u0 + u1;
                    q += u0 * u0 + u1 * u1;
                }
#pragma unroll
                for (int o = 1; o < 4; o <<= 1) {
                    s += __shfl_xor_sync(0xffffffffu, s, o);
                    q += __shfl_xor_sync(0xffffffffu, q, o);
                }
                rs[mt * 2 + h2] = s;
                rq[mt * 2 + h2] = q;
            }
        }
        if ((lane & 3) == 0) {
            const int rg = lane >> 2;
#pragma unroll
            for (int mt = 0; mt < 4; ++mt)
#pragma unroll
                for (int h2 = 0; h2 < 2; ++h2) {
                    const int rl = warp_m * 64 + mt * 16 + h2 * 8 + rg;
                    sbuf[(warp_n * 128 + rl) * 2 + 0] = rs[mt * 2 + h2];
                    sbuf[(warp_n * 128 + rl) * 2 + 1] = rq[mt * 2 + h2];
                }
        }
        __syncthreads();
#pragma unroll
        for (int mt = 0; mt < 4; ++mt) {
#pragma unroll
            for (int h2 = 0; h2 < 2; ++h2) {
                const int rl = warp_m * 64 + mt * 16 + h2 * 8 + (lane >> 2);
                float s = 0.f, q = 0.f;
#pragma unroll
                for (int w = 0; w < 4; ++w) {
                    s += sbuf[(w * 128 + rl) * 2 + 0];
                    q += sbuf[(w * 128 + rl) * 2 + 1];
                }
                const float mu = s * (1.f / 256.f);
                const float var = q * (1.f / 256.f) - mu * mu;
                rs[mt * 2 + h2] = mu;
                rq[mt * 2 + h2] = rsqrtf(var + 1e-5f);
            }
        }
#pragma unroll
        for (int mt = 0; mt < 4; ++mt) {
#pragma unroll
            for (int nt = 0; nt < 8; ++nt) {
                const int c = ocol + nt * 8;
                const float2 gg = *(const float2*)&lng[c];
                const float2 bb = *(const float2*)&lnb[c];
#pragma unroll
                for (int h2 = 0; h2 < 2; ++h2) {
                    const int r = orow + mt * 16 + h2 * 8;
                    const float mu = rs[mt * 2 + h2];
                    const float rd = rq[mt * 2 + h2];
                    float v0 = (acc[mt][nt][h2 * 2]     - mu) * rd * gg.x + bb.x;
                    float v1 = (acc[mt][nt][h2 * 2 + 1] - mu) * rd * gg.y + bb.y;
                    if (OUTM == 2) {
                        *(__half2*)&outH[(size_t)r * 256 + c] = __floats2half2_rn(v0, v1);
                    } else {
                        const float2 rr = *(const float2*)&res[(size_t)r * 256 + c];
                        float2 u; u.x = v0 + rr.x; u.y = v1 + rr.y;
                        *(float2*)&outF[(size_t)r * 256 + c] = u;
                    }
                }
            }
        }
    }
}

// ===========================================================================
// aux kernels
// ===========================================================================
__global__ void split_kernel(const float* __restrict__ in,
                             __half* __restrict__ out, int n4)
{
    int i = blockIdx.x * blockDim.x + threadIdx.x;
    if (i >= n4) return;
    float4 v = ((const float4*)in)[i];
    ((__half2*)out)[i * 2 + 0] = __floats2half2_rn(v.x, v.y);
    ((__half2*)out)[i * 2 + 1] = __floats2half2_rn(v.z, v.w);
}

// all weights in one launch, transposed to [N, K] fp16.
__global__ void wprep_all(const float* __restrict__ Wq, const float* __restrict__ Wk,
                          const float* __restrict__ Wv, const float* __restrict__ Wm,
                          const float* __restrict__ W2, const float* __restrict__ W1,
                          __half* __restrict__ dst)
{
    int idx = blockIdx.x * blockDim.x + threadIdx.x;
    const float* W; int K; int within; __half* o;
    if (idx < 327680) {
        int w = idx >> 16; within = idx & 65535; K = 256;
        const float* srcs[5] = {Wq, Wk, Wv, Wm, W2};
        W = srcs[w];
        o = dst + w * 65536;
    } else if (idx < 458752) {
        within = idx - 327680; K = 512; W = W1;
        o = dst + 327680;
    } else return;
    int nn = within / K, kk = within % K;
    o[(size_t)nn * K + kk] = __float2half_rn(W[(size_t)kk * 256 + nn]);
}

__global__ void zero_kernel(float* p, int n)
{
    int i = blockIdx.x * blockDim.x + threadIdx.x;
    if (i < n) p[i] = 0.f;
}

__global__ __launch_bounds__(1024) void kv_reduce_kernel(
    const float* __restrict__ Kp, const float* __restrict__ Vp,
    float* __restrict__ KV, float* __restrict__ Ksum, int L)
{
    const int nh = blockIdx.x;
    const int n  = nh >> 3;
    const int h  = nh & 7;
    const int rows = L / gridDim.y;        // 256
    const int l0 = blockIdx.y * rows;
    const int tid = threadIdx.x;
    const int d = tid >> 5;
    const int e = tid & 31;

    __shared__ float sk[64][32];
    __shared__ float sv[64][32];

    const size_t base = (size_t)n * L * 256 + h * 32;

    float acc = 0.f, ks = 0.f;
    for (int l = l0; l < l0 + rows; l += 64) {
        __syncthreads();
#pragma unroll
        for (int c = 0; c < 4; ++c) {
            const int idx = tid + c * 1024;
            const int row = idx >> 6;
            const int col = idx & 63;
            size_t off = base + (size_t)(l + row) * 256;
            if (col < 32) sk[row][col] = Kp[off + col];
            else          sv[row][col - 32] = Vp[off + col - 32];
        }
        __syncthreads();
#pragma unroll
        for (int r = 0; r < 64; ++r) acc += sk[r][d] * sv[r][e];
        if (e == 0) {
#pragma unroll
            for (int r = 0; r < 64; ++r) ks += sk[r][d];
        }
    }
    atomicAdd(&KV[(size_t)nh * 1024 + d * 32 + e], acc);
    if (e == 0) atomicAdd(&Ksum[nh * 32 + d], ks);
}

__global__ __launch_bounds__(256) void msg_kernel(
    const float* __restrict__ Q, const float* __restrict__ KV,
    const float* __restrict__ Ksum,
    __half* __restrict__ MH, int L)
{
    const int row = blockIdx.x;
    const int n = row / L;
    const int tid = threadIdx.x;
    const int h = tid >> 5;
    const int e = tid & 31;

    __shared__ float qs[256];
    qs[tid] = Q[(size_t)row * 256 + tid];
    __syncthreads();

    float p = qs[h * 32 + e] * Ksum[(n * 8 + h) * 32 + e];
#pragma unroll
    for (int o = 16; o; o >>= 1) p += __shfl_xor_sync(0xffffffffu, p, o);
    const float z = 1.f / (p + 1e-6f);

    const float* kv = KV + (size_t)(n * 8 + h) * 1024;
    float acc = 0.f;
#pragma unroll
    for (int dd = 0; dd < 32; ++dd) acc += qs[h * 32 + dd] * kv[dd * 32 + e];

    MH[(size_t)row * 256 + tid] = __float2half_rn(acc * z);
}

// ===========================================================================
// launch
// ===========================================================================
extern "C" void kernel_launch(void* const* d_in, const int* in_sizes, int n_in,
                              void* d_out, int out_size)
{
    const float* x  = (const float*)d_in[0];
    const float* Wq = (const float*)d_in[1];
    const float* Wk = (const float*)d_in[2];
    const float* Wv = (const float*)d_in[3];
    const float* Wm = (const float*)d_in[4];
    const float* W1 = (const float*)d_in[5];
    const float* W2 = (const float*)d_in[6];
    const float* g1 = (const float*)d_in[7];
    const float* b1 = (const float*)d_in[8];
    const float* g2 = (const float*)d_in[9];
    const float* b2 = (const float*)d_in[10];

    const int M = in_sizes[0] / C_DIM;   // 65536
    const int L = M / NB;                // 16384

    float *Qf, *Kf, *Vf, *sm;
    __half *xh, *mh, *lh, *hh, *gw;
    cudaGetSymbolAddress((void**)&Qf, g_Q);
    cudaGetSymbolAddress((void**)&Kf, g_K);
    cudaGetSymbolAddress((void**)&Vf, g_V);
    cudaGetSymbolAddress((void**)&xh, g_xh);
    cudaGetSymbolAddress((void**)&mh, g_mh);
    cudaGetSymbolAddress((void**)&lh, g_lh);
    cudaGetSymbolAddress((void**)&hh, g_hh);
    cudaGetSymbolAddress((void**)&gw, g_w);
    cudaGetSymbolAddress((void**)&sm, g_small);
    float* KV   = sm;
    float* Ksum = sm + 32 * 1024;

    __half *wq = gw;
    __half *wk = gw + 65536;
    __half *wv = gw + 131072;
    __half *wm = gw + 196608;
    __half *w2 = gw + 262144;
    __half *w1 = gw + 327680;

    cudaFuncSetAttribute(gemm_mma<256, 1, 0>, cudaFuncAttributeMaxDynamicSharedMemorySize, GEMM_SMEM);
    cudaFuncSetAttribute(gemm_mma<256, 0, 0>, cudaFuncAttributeMaxDynamicSharedMemorySize, GEMM_SMEM);
    cudaFuncSetAttribute(gemm_mma<256, 0, 2>, cudaFuncAttributeMaxDynamicSharedMemorySize, GEMM_SMEM);
    cudaFuncSetAttribute(gemm_mma<512, 2, 1>, cudaFuncAttributeMaxDynamicSharedMemorySize, GEMM_SMEM);
    cudaFuncSetAttribute(gemm_mma<256, 0, 3>, cudaFuncAttributeMaxDynamicSharedMemorySize, GEMM_SMEM);

    wprep_all<<<(458752 + 255) / 256, 256>>>(Wq, Wk, Wv, Wm, W2, W1, gw);
    split_kernel<<<(M * 64 + 255) / 256, 256>>>(x, xh, M * 64);

    const int GB = M / 128;   // 512 CTAs, full N per CTA

    gemm_mma<256, 1, 0><<<GB, 256, GEMM_SMEM>>>(xh, nullptr, wq, Qf, nullptr, nullptr, nullptr, nullptr);
    gemm_mma<256, 1, 0><<<GB, 256, GEMM_SMEM>>>(xh, nullptr, wk, Kf, nullptr, nullptr, nullptr, nullptr);
    gemm_mma<256, 0, 0><<<GB, 256, GEMM_SMEM>>>(xh, nullptr, wv, Vf, nullptr, nullptr, nullptr, nullptr);

    zero_kernel<<<(33792 + 255) / 256, 256>>>(sm, 33792);
    kv_reduce_kernel<<<dim3(32, 64), 1024>>>(Kf, Vf, KV, Ksum, L);

    msg_kernel<<<M, 256>>>(Qf, KV, Ksum, mh, L);

    // msg @ Wm with fused LN1 -> lh (fp16)
    gemm_mma<256, 0, 2><<<GB, 256, GEMM_SMEM>>>(mh, nullptr, wm, nullptr, lh, g1, b1, nullptr);

    // relu([x, ln1] @ W1) -> hh (fp16)
    gemm_mma<512, 2, 1><<<GB, 256, GEMM_SMEM>>>(xh, lh, w1, nullptr, hh, nullptr, nullptr, nullptr);

    // h @ W2 with fused LN2 + residual -> d_out (fp32)
    gemm_mma<256, 0, 3><<<GB, 256, GEMM_SMEM>>>(hh, nullptr, w2, (float*)d_out, nullptr, g2, b2, x);
}